// round 14
// baseline (speedup 1.0000x reference)
#include <cuda_runtime.h>
#include <math.h>

#define MAXN 1025
#define BATCH 8
#define C 128
#define NH 8
#define HD 16
#define L 4
#define TKA 128

typedef unsigned long long ull;

// ---------------- packed fp32x2 helpers (sm_103a FFMA2 path) ---------------
__device__ __forceinline__ ull pack2(float lo, float hi) {
    ull r; asm("mov.b64 %0, {%1, %2};" : "=l"(r) : "f"(lo), "f"(hi)); return r;
}
__device__ __forceinline__ float2 unpack2(ull v) {
    float lo, hi; asm("mov.b64 {%0, %1}, %2;" : "=f"(lo), "=f"(hi) : "l"(v));
    return make_float2(lo, hi);
}
__device__ __forceinline__ ull fma2(ull a, ull b, ull c) {
    ull d; asm("fma.rn.f32x2 %0, %1, %2, %3;" : "=l"(d) : "l"(a), "l"(b), "l"(c));
    return d;
}
__device__ __forceinline__ ull mul2(ull a, ull b) {
    ull d; asm("mul.rn.f32x2 %0, %1, %2;" : "=l"(d) : "l"(a), "l"(b));
    return d;
}
__device__ __forceinline__ ull add2(ull a, ull b) {
    ull d; asm("add.rn.f32x2 %0, %1, %2;" : "=l"(d) : "l"(a), "l"(b));
    return d;
}

// ---------------- cp.async helper -------------------------------------------
__device__ __forceinline__ void cp_async16(unsigned saddr, const void* gaddr) {
    asm volatile("cp.async.ca.shared.global [%0], [%1], 16;"
                 :: "r"(saddr), "l"(gaddr));
}
#define CP_COMMIT() asm volatile("cp.async.commit_group;" ::: "memory")
#define CP_WAIT(n)  asm volatile("cp.async.wait_group %0;" :: "n"(n) : "memory")

// ---------------- device scratch (static, allocation-free) ----------------
__device__ float g_X0[BATCH*MAXN*C];
__device__ float g_X1[BATCH*MAXN*C];
__device__ float g_Q [BATCH*NH*MAXN*HD];
__device__ float g_K [BATCH*NH*MAXN*HD];
__device__ float g_V [BATCH*NH*MAXN*HD];
__device__ float g_O [BATCH*MAXN*C];
__device__ float g_H [BATCH*MAXN*512];
__device__ float g_CLSP[BATCH*NH*MAXN];
__device__ float g_WT[768*128];
__device__ int   g_order[BATCH][1024];
__device__ int   g_count[BATCH];
__device__ int   g_mk[3];
__device__ int   g_N;
__device__ int   g_done;

// transpose conv_w (128,768) -> (768,128); also does global init
__global__ void k_transpose(const float* __restrict__ w) {
    int k = blockIdx.x, c = threadIdx.x;
    g_WT[k*128 + c] = w[c*768 + k];
    if (k == 0 && c == 0) {
        g_N = MAXN;
        g_mk[0] = 0; g_mk[1] = 0; g_mk[2] = 0;
        g_done = 0;
    }
}

// ---------------- LN helper (16 tokens, 128 threads) -----------------------
#define LN16_BODY(lwp, lbp)                                                     \
    {                                                                           \
        _Pragma("unroll")                                                       \
        for (int p = 0; p < 16; p++) {                                          \
            float s = xv[p];                                                    \
            _Pragma("unroll")                                                   \
            for (int o = 16; o; o >>= 1) s += __shfl_xor_sync(~0u, s, o);       \
            if (!lane) sRed[0][wid][p] = s;                                     \
        }                                                                       \
        __syncthreads();                                                        \
        _Pragma("unroll")                                                       \
        for (int p = 0; p < 16; p++) {                                          \
            float mu = (sRed[0][0][p] + sRed[0][1][p] + sRed[0][2][p]           \
                        + sRed[0][3][p]) * 0.0078125f;                          \
            float d = xv[p] - mu; xv[p] = d;                                    \
            float s = d * d;                                                    \
            _Pragma("unroll")                                                   \
            for (int o = 16; o; o >>= 1) s += __shfl_xor_sync(~0u, s, o);       \
            if (!lane) sRed[1][wid][p] = s;                                     \
        }                                                                       \
        __syncthreads();                                                        \
        float wgt = (lwp)[tid], bia = (lbp)[tid];                               \
        _Pragma("unroll")                                                       \
        for (int p4 = 0; p4 < 4; p4++) {                                        \
            float4 pk;                                                          \
            float* pkf = (float*)&pk;                                           \
            _Pragma("unroll")                                                   \
            for (int j = 0; j < 4; j++) {                                       \
                int p = 4*p4 + j;                                               \
                float var = (sRed[1][0][p] + sRed[1][1][p] + sRed[1][2][p]      \
                             + sRed[1][3][p]) * 0.0078125f;                     \
                pkf[j] = xv[p] * rsqrtf(var + 1e-5f) * wgt + bia;               \
            }                                                                   \
            sYT[tid][p4] = pk;                                                  \
        }                                                                       \
        __syncthreads();                                                        \
    }

// QKV matmul from sYT + head-major store.
#define QKV_BODY(Wp, bp, writeGuard0, writeGuard1, TOK0, TOK1)                  \
    {                                                                           \
        float b0 = (bp)[tid], b1 = (bp)[tid + 128], b2 = (bp)[tid + 256];       \
        ull a0[8], a1[8], a2[8];                                                \
        ull i0 = pack2(b0, b0), i1 = pack2(b1, b1), i2 = pack2(b2, b2);         \
        _Pragma("unroll")                                                       \
        for (int j = 0; j < 8; j++) { a0[j] = i0; a1[j] = i1; a2[j] = i2; }     \
        _Pragma("unroll 4")                                                     \
        for (int k = 0; k < 128; k++) {                                         \
            float w0 = (Wp)[k*384 + tid];                                       \
            float w1 = (Wp)[k*384 + 128 + tid];                                 \
            float w2 = (Wp)[k*384 + 256 + tid];                                 \
            ull w02 = pack2(w0, w0), w12 = pack2(w1, w1), w22 = pack2(w2, w2);  \
            const ulonglong2* yr = (const ulonglong2*)&sYT[k][0];               \
            ulonglong2 y0 = yr[0], y1 = yr[1], y2 = yr[2], y3 = yr[3];          \
            ull yv8[8] = {y0.x, y0.y, y1.x, y1.y, y2.x, y2.y, y3.x, y3.y};      \
            _Pragma("unroll")                                                   \
            for (int j = 0; j < 8; j++) {                                       \
                a0[j] = fma2(w02, yv8[j], a0[j]);                               \
                a1[j] = fma2(w12, yv8[j], a1[j]);                               \
                a2[j] = fma2(w22, yv8[j], a2[j]);                               \
            }                                                                   \
        }                                                                       \
        int h = tid >> 4, d = tid & 15;                                         \
        size_t hb = (size_t)(b*NH + h)*MAXN;                                    \
        _Pragma("unroll")                                                       \
        for (int j = 0; j < 8; j++) {                                           \
            float2 q2 = unpack2(a0[j]);                                         \
            float2 k2 = unpack2(a1[j]);                                         \
            float2 v2 = unpack2(a2[j]);                                         \
            int p0 = 2*j, p1 = 2*j + 1;                                         \
            if (writeGuard0) {                                                  \
                size_t o = (hb + (TOK0))*HD + d;                                \
                Qo[o] = q2.x; Ko[o] = k2.x; Vo[o] = v2.x;                       \
            }                                                                   \
            if (writeGuard1) {                                                  \
                size_t o = (hb + (TOK1))*HD + d;                                \
                Qo[o] = q2.y; Ko[o] = k2.y; Vo[o] = v2.y;                       \
            }                                                                   \
        }                                                                       \
    }

// slot -> src gather table (16 slots per CTA); slot 0 = CLS
#define GATHER_SETUP(pi)                                                        \
    int mk1 = 1 + g_mk[pi];                                                     \
    if (s0 >= mk1) return;                                                      \
    int tid = threadIdx.x;                                                      \
    __shared__ int sSrc[16];                                                    \
    __shared__ int sVal[16];                                                    \
    if (tid < 16) {                                                             \
        int slot = s0 + tid;                                                    \
        int valid = 0, src = 0;                                                 \
        if (slot == 0) { valid = 1; src = 0; }                                  \
        else if (slot < mk1 && slot - 1 < g_count[b]) {                         \
            valid = 1; src = 1 + g_order[b][slot - 1];                          \
        }                                                                       \
        sSrc[tid] = src; sVal[tid] = valid;                                     \
    }

// ---------------- patch embed + cls + LN1 + QKV (layer 0) -------------------
__global__ void __launch_bounds__(128) k_patchQKV(
        const float* __restrict__ x, const float* __restrict__ cb,
        const float* __restrict__ cls, const float* __restrict__ pos,
        float* __restrict__ X,
        const float* __restrict__ lw, const float* __restrict__ lb,
        const float* __restrict__ W, const float* __restrict__ bias,
        float* __restrict__ Qo, float* __restrict__ Ko, float* __restrict__ Vo) {
    int b = blockIdx.y;
    int tid = threadIdx.x, wid = tid >> 5, lane = tid & 31;
    __shared__ __align__(16) float sPT[768][16];
    __shared__ float4 sYT[128][4];
    __shared__ float sRed[2][4][16];
    float xv[16];
    int ntok, tbase;
    if (blockIdx.x == 64) {
        float v = cls[tid] + pos[tid];
        X[(size_t)b*MAXN*C + tid] = v;
        xv[0] = v;
        #pragma unroll
        for (int p = 1; p < 16; p++) xv[p] = 0.0f;
        ntok = 1; tbase = 0;
    } else {
        int t0 = blockIdx.x * 16;
        for (int v = tid; v < 768*16; v += 128) {
            int p = v & 15, k = v >> 4;
            int t = t0 + p;
            int ph = t >> 5, pw = t & 31;
            int ch = k >> 8, rem = k & 255, py = rem >> 4, px = rem & 15;
            sPT[k][p] = x[((size_t)(b*3 + ch)*512 + ph*16 + py)*512 + pw*16 + px];
        }
        __syncthreads();
        float bias0 = cb[tid];
        ull acc2[8];
        ull bini = pack2(bias0, bias0);
        #pragma unroll
        for (int j = 0; j < 8; j++) acc2[j] = bini;
        #pragma unroll 4
        for (int k = 0; k < 768; k++) {
            float w = g_WT[k*128 + tid];
            ull w2 = pack2(w, w);
            const ulonglong2* yr = (const ulonglong2*)&sPT[k][0];
            ulonglong2 y0 = yr[0], y1 = yr[1], y2 = yr[2], y3 = yr[3];
            acc2[0] = fma2(w2, y0.x, acc2[0]); acc2[1] = fma2(w2, y0.y, acc2[1]);
            acc2[2] = fma2(w2, y1.x, acc2[2]); acc2[3] = fma2(w2, y1.y, acc2[3]);
            acc2[4] = fma2(w2, y2.x, acc2[4]); acc2[5] = fma2(w2, y2.y, acc2[5]);
            acc2[6] = fma2(w2, y3.x, acc2[6]); acc2[7] = fma2(w2, y3.y, acc2[7]);
        }
        #pragma unroll
        for (int j = 0; j < 8; j++) {
            float2 u = unpack2(acc2[j]);
            int t = t0 + 2*j;
            float v0 = u.x + pos[(1 + t)*C + tid];
            float v1 = u.y + pos[(2 + t)*C + tid];
            X[((size_t)b*MAXN + 1 + t)*C + tid] = v0;
            X[((size_t)b*MAXN + 2 + t)*C + tid] = v1;
            xv[2*j] = v0; xv[2*j + 1] = v1;
        }
        ntok = 16; tbase = 1 + t0;
    }
    LN16_BODY(lw, lb)
    QKV_BODY(W, bias, (p0 < ntok), (p1 < ntok), tbase + p0, tbase + p1)
}

// ---------------- LN + qkv -> head-major Q,K,V (layers 1-3) -----------------
__global__ void __launch_bounds__(128) k_qkvln(
        const float* __restrict__ X, const float* __restrict__ lw,
        const float* __restrict__ lb, const float* __restrict__ W,
        const float* __restrict__ bias,
        float* __restrict__ Qo, float* __restrict__ Ko, float* __restrict__ Vo) {
    int b = blockIdx.y;
    int n0 = blockIdx.x * 16;
    int N = g_N;
    if (n0 >= N) return;
    int tid = threadIdx.x, wid = tid >> 5, lane = tid & 31;
    __shared__ float4 sYT[128][4];
    __shared__ float sRed[2][4][16];
    float xv[16];
    #pragma unroll
    for (int p = 0; p < 16; p++) {
        int n = n0 + p;
        xv[p] = (n < N) ? X[((size_t)b*MAXN + n)*C + tid] : 0.0f;
    }
    LN16_BODY(lw, lb)
    QKV_BODY(W, bias, (n0 + p0 < N), (n0 + p1 < N), n0 + p0, n0 + p1)
}

// ---------------- attention v8: split-K + cp.async double buffering ---------
__global__ void __launch_bounds__(128) k_attn8(
        const float* __restrict__ Q, const float* __restrict__ K,
        const float* __restrict__ V, float* __restrict__ O) {
    int N = g_N;
    int bh = blockIdx.y;
    int b = bh >> 3, h = bh & 7;
    int q0 = blockIdx.x * 64;
    if (q0 >= N) return;
    int tid = threadIdx.x, w = tid >> 5, lane = tid & 31;

    __shared__ __align__(16) float sMem[8192];
    unsigned sBase = (unsigned)__cvta_generic_to_shared(sMem);

    const float4* K4 = (const float4*)(K + (size_t)bh*MAXN*HD);
    const float4* V4 = (const float4*)(V + (size_t)bh*MAXN*HD);
    int qA = q0 + lane;
    int qB = q0 + 32 + lane;
    bool vA = qA < N, vB = qB < N;

    ull qa[8], qb[8];
    ull qs = pack2(0.25f, 0.25f);
    #pragma unroll
    for (int j = 0; j < 8; j++) { qa[j] = 0ull; qb[j] = 0ull; }
    if (vA) {
        const float4* Q4 = (const float4*)(Q + ((size_t)bh*MAXN + qA)*HD);
        #pragma unroll
        for (int j = 0; j < 4; j++) {
            float4 t = Q4[j];
            qa[2*j]   = mul2(pack2(t.x, t.y), qs);
            qa[2*j+1] = mul2(pack2(t.z, t.w), qs);
        }
    }
    if (vB) {
        const float4* Q4 = (const float4*)(Q + ((size_t)bh*MAXN + qB)*HD);
        #pragma unroll
        for (int j = 0; j < 4; j++) {
            float4 t = Q4[j];
            qb[2*j]   = mul2(pack2(t.x, t.y), qs);
            qb[2*j+1] = mul2(pack2(t.z, t.w), qs);
        }
    }

    float lA = 0.0f, lB = 0.0f;
    ull accA[8], accB[8];
    #pragma unroll
    for (int j = 0; j < 8; j++) { accA[j] = 0ull; accB[j] = 0ull; }

    int nt = (N + TKA - 1) / TKA;

    {
        int kn0 = min(TKA, N);
        int lim = kn0 * 4;
        for (int i = tid; i < lim; i += 128) {
            unsigned dk = sBase + ((unsigned)i << 4);
            unsigned dv = dk + 8192u;
            cp_async16(dk, K4 + i);
            cp_async16(dv, V4 + i);
        }
        CP_COMMIT();
    }

    for (int t = 0; t < nt; t++) {
        int cur = t & 1;
        if (t + 1 < nt) {
            int nb = (t + 1) * TKA;
            int knn = min(TKA, N - nb);
            int lim = knn * 4;
            unsigned so = sBase + (unsigned)((cur ^ 1) * 16384);
            const float4* gk = K4 + nb*4;
            const float4* gv = V4 + nb*4;
            for (int i = tid; i < lim; i += 128) {
                unsigned dk = so + ((unsigned)i << 4);
                unsigned dv = dk + 8192u;
                cp_async16(dk, gk + i);
                cp_async16(dv, gv + i);
            }
            CP_COMMIT();
            CP_WAIT(1);
        } else {
            CP_WAIT(0);
        }
        __syncthreads();

        int base = t * TKA;
        int kn = min(TKA, N - base);
        const float4* sK = (const float4*)(sMem + cur*4096);
        const float4* sV = (const float4*)(sMem + cur*4096 + 2048);
        int lo = w * 32;
        int hi = min(kn, lo + 32);
        #pragma unroll 2
        for (int m = lo; m < hi; m++) {
            const ulonglong2* kp = (const ulonglong2*)&sK[m*4];
            ulonglong2 k0 = kp[0], k1 = kp[1], k2 = kp[2], k3 = kp[3];
            ull sa = fma2(qa[1], k0.y, mul2(qa[0], k0.x));
            ull sb = fma2(qa[3], k1.y, mul2(qa[2], k1.x));
            ull sc = fma2(qa[5], k2.y, mul2(qa[4], k2.x));
            ull sd = fma2(qa[7], k3.y, mul2(qa[6], k3.x));
            ull stA = add2(add2(sa, sb), add2(sc, sd));
            ull ta = fma2(qb[1], k0.y, mul2(qb[0], k0.x));
            ull tb = fma2(qb[3], k1.y, mul2(qb[2], k1.x));
            ull tc = fma2(qb[5], k2.y, mul2(qb[4], k2.x));
            ull td = fma2(qb[7], k3.y, mul2(qb[6], k3.x));
            ull stB = add2(add2(ta, tb), add2(tc, td));
            float2 spA = unpack2(stA);
            float2 spB = unpack2(stB);
            float eA = __expf(spA.x + spA.y);
            float eB = __expf(spB.x + spB.y);
            lA += eA; lB += eB;
            ull eA2 = pack2(eA, eA);
            ull eB2 = pack2(eB, eB);
            const ulonglong2* vp = (const ulonglong2*)&sV[m*4];
            ulonglong2 v0 = vp[0], v1 = vp[1], v2 = vp[2], v3 = vp[3];
            accA[0] = fma2(eA2, v0.x, accA[0]); accB[0] = fma2(eB2, v0.x, accB[0]);
            accA[1] = fma2(eA2, v0.y, accA[1]); accB[1] = fma2(eB2, v0.y, accB[1]);
            accA[2] = fma2(eA2, v1.x, accA[2]); accB[2] = fma2(eB2, v1.x, accB[2]);
            accA[3] = fma2(eA2, v1.y, accA[3]); accB[3] = fma2(eB2, v1.y, accB[3]);
            accA[4] = fma2(eA2, v2.x, accA[4]); accB[4] = fma2(eB2, v2.x, accB[4]);
            accA[5] = fma2(eA2, v2.y, accA[5]); accB[5] = fma2(eB2, v2.y, accB[5]);
            accA[6] = fma2(eA2, v3.x, accA[6]); accB[6] = fma2(eB2, v3.x, accB[6]);
            accA[7] = fma2(eA2, v3.y, accA[7]); accB[7] = fma2(eB2, v3.y, accB[7]);
        }
        __syncthreads();
    }

    float (*sAcc)[64][17] = (float (*)[64][17])sMem;

    #pragma unroll
    for (int j = 0; j < 8; j++) {
        float2 uA = unpack2(accA[j]);
        float2 uB = unpack2(accB[j]);
        sAcc[w][lane][2*j]      = uA.x;
        sAcc[w][lane][2*j+1]    = uA.y;
        sAcc[w][32+lane][2*j]   = uB.x;
        sAcc[w][32+lane][2*j+1] = uB.y;
    }
    sAcc[w][lane][16]    = lA;
    sAcc[w][32+lane][16] = lB;
    __syncthreads();

    int j = tid >> 1, half = tid & 1;
    int q = q0 + j;
    if (q < N) {
        float lsum = (sAcc[0][j][16] + sAcc[1][j][16])
                   + (sAcc[2][j][16] + sAcc[3][j][16]);
        float inv = 1.0f / lsum;
        int d0 = half * 8;
        float o[8];
        #pragma unroll
        for (int d = 0; d < 8; d++) {
            o[d] = ((sAcc[0][j][d0+d] + sAcc[1][j][d0+d])
                  + (sAcc[2][j][d0+d] + sAcc[3][j][d0+d])) * inv;
        }
        float* op = O + ((size_t)b*MAXN + q)*C + h*HD + d0;
        ((float4*)op)[0] = make_float4(o[0], o[1], o[2], o[3]);
        ((float4*)op)[1] = make_float4(o[4], o[5], o[6], o[7]);
        if (!half) {
            const float4* Q4 = (const float4*)(Q + ((size_t)bh*MAXN + q)*HD);
            float qv[16];
            #pragma unroll
            for (int i = 0; i < 4; i++) {
                float4 tq = Q4[i];
                qv[4*i]   = tq.x * 0.25f; qv[4*i+1] = tq.y * 0.25f;
                qv[4*i+2] = tq.z * 0.25f; qv[4*i+3] = tq.w * 0.25f;
            }
            const float* k0 = K + (size_t)bh*MAXN*HD;
            float sa_l = fmaf(qv[2],  k0[2],  qv[0]*k0[0]);
            float sa_h = fmaf(qv[3],  k0[3],  qv[1]*k0[1]);
            float sb_l = fmaf(qv[6],  k0[6],  qv[4]*k0[4]);
            float sb_h = fmaf(qv[7],  k0[7],  qv[5]*k0[5]);
            float sc_l = fmaf(qv[10], k0[10], qv[8]*k0[8]);
            float sc_h = fmaf(qv[11], k0[11], qv[9]*k0[9]);
            float sd_l = fmaf(qv[14], k0[14], qv[12]*k0[12]);
            float sd_h = fmaf(qv[15], k0[15], qv[13]*k0[13]);
            float slo = (sa_l + sb_l) + (sc_l + sd_l);
            float shi = (sa_h + sb_h) + (sc_h + sd_h);
            g_CLSP[(size_t)bh*MAXN + q] = __expf(slo + shi) * inv;
        }
    }
}

// ---------------- prune (warp-shuffle scan/argmax + folded g_N) -------------
__global__ void k_prune1(float thresh, int pi) {
    int b = blockIdx.x;
    int t = threadIdx.x;
    int lane = t & 31, wid = t >> 5;
    int tc = g_N - 1;
    float am = -1e30f;
    int keep = 0;
    if (t < tc) {
        float s = 0.0f;
        #pragma unroll
        for (int h = 0; h < NH; h++) s += g_CLSP[(b*NH + h)*MAXN + 1 + t];
        am = s * 0.125f;
        keep = (am > thresh) ? 1 : 0;
    }
    int sc = keep;
    #pragma unroll
    for (int o = 1; o < 32; o <<= 1) {
        int v = __shfl_up_sync(~0u, sc, o);
        if (lane >= o) sc += v;
    }
    float bv = am; int bi = t;
    #pragma unroll
    for (int o = 16; o; o >>= 1) {
        float ov = __shfl_xor_sync(~0u, bv, o);
        int   oi = __shfl_xor_sync(~0u, bi, o);
        if (ov > bv || (ov == bv && oi < bi)) { bv = ov; bi = oi; }
    }
    __shared__ int wsum[32], wbi[32], woff[32];
    __shared__ float wbv[32];
    __shared__ int gArg, gTot;
    if (lane == 31) wsum[wid] = sc;
    if (lane == 0) { wbv[wid] = bv; wbi[wid] = bi; }
    __syncthreads();
    if (wid == 0) {
        int v = wsum[lane];
        int s2 = v;
        #pragma unroll
        for (int o = 1; o < 32; o <<= 1) {
            int u = __shfl_up_sync(~0u, s2, o);
            if (lane >= o) s2 += u;
        }
        woff[lane] = s2 - v;
        if (lane == 31) gTot = s2;
        float bv2 = wbv[lane]; int bi2 = wbi[lane];
        #pragma unroll
        for (int o = 16; o; o >>= 1) {
            float ov = __shfl_xor_sync(~0u, bv2, o);
            int   oi = __shfl_xor_sync(~0u, bi2, o);
            if (ov > bv2 || (ov == bv2 && oi < bi2)) { bv2 = ov; bi2 = oi; }
        }
        if (lane == 0) gArg = bi2;
    }
    __syncthreads();
    int total = gTot;
    int posi = woff[wid] + sc;
    if (total > 0 && keep) g_order[b][posi - 1] = t;
    if (t == 0) {
        int cnt = total;
        if (total == 0) { g_order[b][0] = gArg; cnt = 1; }
        g_count[b] = cnt;
        atomicMax(&g_mk[pi], cnt);
        __threadfence();
        int tk = atomicAdd(&g_done, 1);
        if (tk == BATCH - 1) {
            g_N = 1 + g_mk[pi];
            g_done = 0;
        }
    }
}

// ---------- fused gathered proj + LN2 + fc1 + gelu (layers 0-2) -------------
__global__ void __launch_bounds__(128) k_pf1G(
        const float* __restrict__ Oin, const float* __restrict__ Wp,
        const float* __restrict__ bp, float* __restrict__ X,
        const float* __restrict__ lw, const float* __restrict__ lb,
        const float* __restrict__ W1, const float* __restrict__ b1,
        float* __restrict__ H, int pi) {
    int b = blockIdx.y;
    int s0 = blockIdx.x * 16;
    GATHER_SETUP(pi)
    int wid = tid >> 5, lane = tid & 31;
    __shared__ __align__(16) float sOT[128][16];
    __shared__ float4 sYT[128][4];
    __shared__ float sRed[2][4][16];
    __syncthreads();
    const float4* O4 = (const float4*)Oin;
    for (int v = tid; v < 16*32; v += 128) {
        int p = v & 15, kq = v >> 4;
        float4 o4 = sVal[p] ? O4[((size_t)b*MAXN + sSrc[p])*32 + kq]
                            : make_float4(0.f, 0.f, 0.f, 0.f);
        sOT[4*kq+0][p] = o4.x; sOT[4*kq+1][p] = o4.y;
        sOT[4*kq+2][p] = o4.z; sOT[4*kq+3][p] = o4.w;
    }
    __syncthreads();
    float bs = bp[tid];
    ull acc2[8];
    ull bini = pack2(bs, bs);
    #pragma unroll
    for (int j = 0; j < 8; j++) acc2[j] = bini;
    #pragma unroll 4
    for (int k = 0; k < 128; k++) {
        float w = Wp[k*128 + tid];
        ull w2 = pack2(w, w);
        const ulonglong2* yr = (const ulonglong2*)&sOT[k][0];
        ulonglong2 y0 = yr[0], y1 = yr[1], y2 = yr[2], y3 = yr[3];
        acc2[0] = fma2(w2, y0.x, acc2[0]); acc2[1] = fma2(w2, y0.y, acc2[1]);
        acc2[2] = fma2(w2, y1.x, acc2[2]); acc2[3] = fma2(w2, y1.y, acc2[3]);
        acc2[4] = fma2(w2, y2.x, acc2[4]); acc2[5] = fma2(w2, y2.y, acc2[5]);
        acc2[6] = fma2(w2, y3.x, acc2[6]); acc2[7] = fma2(w2, y3.y, acc2[7]);
    }
    float xv[16];
    #pragma unroll
    for (int j = 0; j < 8; j++) {
        float2 u = unpack2(acc2[j]);
        int p0 = 2*j, p1 = 2*j + 1;
        if (sVal[p0]) {
            float t0 = X[((size_t)b*MAXN + sSrc[p0])*C + tid] + u.x;
            X[((size_t)b*MAXN + sSrc[p0])*C + tid] = t0;
            xv[p0] = t0;
        } else xv[p0] = 0.0f;
        if (sVal[p1]) {
            float t1 = X[((size_t)b*MAXN + sSrc[p1])*C + tid] + u.y;
            X[((size_t)b*MAXN + sSrc[p1])*C + tid] = t1;
            xv[p1] = t1;
        } else xv[p1] = 0.0f;
    }
    LN16_BODY(lw, lb)
    const float4* W4 = (const float4*)W1;
    float4 b4 = ((const float4*)b1)[tid];
    ull a0[8], a1[8], a2[8], a3[8];
    ull i0 = pack2(b4.x, b4.x), i1 = pack2(b4.y, b4.y);
    ull i2 = pack2(b4.z, b4.z), i3 = pack2(b4.w, b4.w);
    #pragma unroll
    for (int j = 0; j < 8; j++) { a0[j]=i0; a1[j]=i1; a2[j]=i2; a3[j]=i3; }
    #pragma unroll 2
    for (int k = 0; k < 128; k++) {
        float4 w4 = W4[k*128 + tid];
        ull w0 = pack2(w4.x, w4.x), w1 = pack2(w4.y, w4.y);
        ull w2 = pack2(w4.z, w4.z), w3 = pack2(w4.w, w4.w);
        const ulonglong2* yr = (const ulonglong2*)&sYT[k][0];
        ulonglong2 y0 = yr[0], y1 = yr[1], y2 = yr[2], y3 = yr[3];
        ull yv8[8] = {y0.x, y0.y, y1.x, y1.y, y2.x, y2.y, y3.x, y3.y};
        #pragma unroll
        for (int j = 0; j < 8; j++) {
            a0[j] = fma2(w0, yv8[j], a0[j]);
            a1[j] = fma2(w1, yv8[j], a1[j]);
            a2[j] = fma2(w2, yv8[j], a2[j]);
            a3[j] = fma2(w3, yv8[j], a3[j]);
        }
    }
    float4* H4 = (float4*)H;
    #pragma unroll
    for (int j = 0; j < 8; j++) {
        float2 u0 = unpack2(a0[j]);
        float2 u1 = unpack2(a1[j]);
        float2 u2 = unpack2(a2[j]);
        float2 u3 = unpack2(a3[j]);
        int slot = s0 + 2*j;
        if (slot < mk1) {
            float4 hv;
            hv.x = 0.5f*u0.x*(1.0f + erff(u0.x*0.70710678118654752f));
            hv.y = 0.5f*u1.x*(1.0f + erff(u1.x*0.70710678118654752f));
            hv.z = 0.5f*u2.x*(1.0f + erff(u2.x*0.70710678118654752f));
            hv.w = 0.5f*u3.x*(1.0f + erff(u3.x*0.70710678118654752f));
            H4[((size_t)b*MAXN + slot)*128 + tid] = hv;
        }
        if (slot + 1 < mk1) {
            float4 hv;
            hv.x = 0.5f*u0.y*(1.0f + erff(u0.y*0.70710678118654752f));
            hv.y = 0.5f*u1.y*(1.0f + erff(u1.y*0.70710678118654752f));
            hv.z = 0.5f*u2.y*(1.0f + erff(u2.y*0.70710678118654752f));
            hv.w = 0.5f*u3.y*(1.0f + erff(u3.y*0.70710678118654752f));
            H4[((size_t)b*MAXN + slot + 1)*128 + tid] = hv;
        }
    }
}

// ---------- fused dense proj + LN2 + fc1 + gelu (layer 3) -------------------
__global__ void __launch_bounds__(128) k_pf1D(
        const float* __restrict__ Oin, const float* __restrict__ Wp,
        const float* __restrict__ bp, float* __restrict__ X,
        const float* __restrict__ lw, const float* __restrict__ lb,
        const float* __restrict__ W1, const float* __restrict__ b1,
        float* __restrict__ H) {
    int b = blockIdx.y;
    int n0 = blockIdx.x * 16;
    int N = g_N;
    if (n0 >= N) return;
    int tid = threadIdx.x, wid = tid >> 5, lane = tid & 31;
    __shared__ __align__(16) float sOT[128][16];
    __shared__ float4 sYT[128][4];
    __shared__ float sRed[2][4][16];
    const float4* O4 = (const float4*)Oin;
    for (int v = tid; v < 16*32; v += 128) {
        int p = v & 15, kq = v >> 4;
        int n = n0 + p;
        float4 o4 = (n < N) ? O4[((size_t)b*MAXN + n)*32 + kq]
                            : make_float4(0.f, 0.f, 0.f, 0.f);
        sOT[4*kq+0][p] = o4.x; sOT[4*kq+1][p] = o4.y;
        sOT[4*kq+2][p] = o4.z; sOT[4*kq+3][p] = o4.w;
    }
    __syncthreads();
    float bs = bp[tid];
    ull acc2[8];
    ull bini = pack2(bs, bs);
    #pragma unroll
    for (int j = 0; j < 8; j++) acc2[j] = bini;
    #pragma unroll 4
    for (int k = 0; k < 128; k++) {
        float w = Wp[k*128 + tid];
        ull w2 = pack2(w, w);
        const ulonglong2* yr = (const ulonglong2*)&sOT[k][0];
        ulonglong2 y0 = yr[0], y1 = yr[1], y2 = yr[2], y3 = yr[3];
        acc2[0] = fma2(w2, y0.x, acc2[0]); acc2[1] = fma2(w2, y0.y, acc2[1]);
        acc2[2] = fma2(w2, y1.x, acc2[2]); acc2[3] = fma2(w2, y1.y, acc2[3]);
        acc2[4] = fma2(w2, y2.x, acc2[4]); acc2[5] = fma2(w2, y2.y, acc2[5]);
        acc2[6] = fma2(w2, y3.x, acc2[6]); acc2[7] = fma2(w2, y3.y, acc2[7]);
    }
    float xv[16];
    #pragma unroll
    for (int j = 0; j < 8; j++) {
        float2 u = unpack2(acc2[j]);
        int n = n0 + 2*j;
        if (n < N) {
            float t0 = X[((size_t)b*MAXN + n)*C + tid] + u.x;
            X[((size_t)b*MAXN + n)*C + tid] = t0;
            xv[2*j] = t0;
        } else xv[2*j] = 0.0f;
        if (n + 1 < N) {
            float t1 = X[((size_t)b*MAXN + n + 1)*C + tid] + u.y;
            X[((size_t)b*MAXN + n + 1)*C + tid] = t1;
            xv[2*j+1] = t1;
        } else xv[2*j+1] = 0.0f;
    }
    LN16_BODY(lw, lb)
    const float4* W4 = (const float4*)W1;
    float4 b4 = ((const float4*)b1)[tid];
    ull a0[8], a1[8], a2[8], a3[8];
    ull i0 = pack2(b4.x, b4.x), i1 = pack2(b4.y, b4.y);
    ull i2 = pack2(b4.z, b4.z), i3 = pack2(b4.w, b4.w);
    #pragma unroll
    for (int j = 0; j < 8; j++) { a0[j]=i0; a1[j]=i1; a2[j]=i2; a3[j]=i3; }
    #pragma unroll 2
    for (int k = 0; k < 128; k++) {
        float4 w4 = W4[k*128 + tid];
        ull w0 = pack2(w4.x, w4.x), w1 = pack2(w4.y, w4.y);
        ull w2 = pack2(w4.z, w4.z), w3 = pack2(w4.w, w4.w);
        const ulonglong2* yr = (const ulonglong2*)&sYT[k][0];
        ulonglong2 y0 = yr[0], y1 = yr[1], y2 = yr[2], y3 = yr[3];
        ull yv8[8] = {y0.x, y0.y, y1.x, y1.y, y2.x, y2.y, y3.x, y3.y};
        #pragma unroll
        for (int j = 0; j < 8; j++) {
            a0[j] = fma2(w0, yv8[j], a0[j]);
            a1[j] = fma2(w1, yv8[j], a1[j]);
            a2[j] = fma2(w2, yv8[j], a2[j]);
            a3[j] = fma2(w3, yv8[j], a3[j]);
        }
    }
    float4* H4 = (float4*)H;
    #pragma unroll
    for (int j = 0; j < 8; j++) {
        float2 u0 = unpack2(a0[j]);
        float2 u1 = unpack2(a1[j]);
        float2 u2 = unpack2(a2[j]);
        float2 u3 = unpack2(a3[j]);
        int n = n0 + 2*j;
        if (n < N) {
            float4 hv;
            hv.x = 0.5f*u0.x*(1.0f + erff(u0.x*0.70710678118654752f));
            hv.y = 0.5f*u1.x*(1.0f + erff(u1.x*0.70710678118654752f));
            hv.z = 0.5f*u2.x*(1.0f + erff(u2.x*0.70710678118654752f));
            hv.w = 0.5f*u3.x*(1.0f + erff(u3.x*0.70710678118654752f));
            H4[((size_t)b*MAXN + n)*128 + tid] = hv;
        }
        if (n + 1 < N) {
            float4 hv;
            hv.x = 0.5f*u0.y*(1.0f + erff(u0.y*0.70710678118654752f));
            hv.y = 0.5f*u1.y*(1.0f + erff(u1.y*0.70710678118654752f));
            hv.z = 0.5f*u2.y*(1.0f + erff(u2.y*0.70710678118654752f));
            hv.w = 0.5f*u3.y*(1.0f + erff(u3.y*0.70710678118654752f));
            H4[((size_t)b*MAXN + n + 1)*128 + tid] = hv;
        }
    }
}

// ---------------- gathered fc2 (layers 0-2): compact + residual + pos -------
__global__ void __launch_bounds__(128) k_fc2G(
        const float* __restrict__ H, const float* __restrict__ W,
        const float* __restrict__ bias, const float* __restrict__ Xold,
        float* __restrict__ Xnew, const float* __restrict__ pos, int pi) {
    int b = blockIdx.y;
    int s0 = blockIdx.x * 16;
    GATHER_SETUP(pi)
    __shared__ __align__(16) float sHT[512][16];
    __syncthreads();
    const float4* H4 = (const float4*)H;
    for (int v = tid; v < 16*128; v += 128) {
        int p = v & 15, kq = v >> 4;
        int slot = s0 + p;
        float4 h4 = (slot < mk1) ? H4[((size_t)b*MAXN + slot)*128 + kq]
                                 : make_float4(0.f, 0.f, 0.f, 0.f);
        sHT[4*kq+0][p] = h4.x; sHT[4*kq+1][p] = h4.y;
        sHT[4*kq+2][p] = h4.z; sHT[4*kq+3][p] = h4.w;
    }
    __syncthreads();
    float bs = bias[tid];
    ull acc2[8];
    ull bini = pack2(bs, bs);
    #pragma unroll
    for (int j = 0; j < 8; j++) acc2[j] = bini;
    #pragma unroll 4
    for (int k = 0; k < 512; k++) {
        float w = W[k*128 + tid];
        ull w2 = pack2(w, w);
        const ulonglong2* yr = (const ulonglong2*)&sHT[k][0];
        ulonglong2 y0 = yr[0], y1 = yr[1], y2 = yr[2], y3 = yr[3];
        acc2[0] = fma2(w2, y0.x, acc2[0]); acc2[1] = fma2(w2, y0.y, acc2[1]);
        acc2[2] = fma2(w2, y1.x, acc2[2]); acc2[3] = fma2(w2, y1.y, acc2[3]);
        acc2[4] = fma2(w2, y2.x, acc2[4]); acc2[5] = fma2(w2, y2.y, acc2[5]);
        acc2[6] = fma2(w2, y3.x, acc2[6]); acc2[7] = fma2(w2, y3.y, acc2[7]);
    }
    #pragma unroll
    for (int j = 0; j < 8; j++) {
        float2 u = unpack2(acc2[j]);
        int p0 = 2*j, p1 = 2*j + 1;
        int slot0 = s0 + p0, slot1 = s0 + p1;
        if (slot0 < mk1) {
            float base = sVal[p0]
                ? Xold[((size_t)b*MAXN + sSrc[p0])*C + tid] + u.x : 0.0f;
            Xnew[((size_t)b*MAXN + slot0)*C + tid] = base + pos[slot0*C + tid];
        }
        if (slot1 < mk1) {
            float base = sVal[p1]
                ? Xold[((size_t)b*MAXN + sSrc[p1])*C + tid] + u.y : 0.0f;
            Xnew[((size_t)b*MAXN + slot1)*C + tid] = base + pos[slot1*C + tid];
        }
    }
}

// ---------------- dense fc2 (layer 3): writes residual sum to out -----------
__global__ void __launch_bounds__(128) k_fc2D(
        const float* __restrict__ H, const float* __restrict__ W,
        const float* __restrict__ bias, const float* __restrict__ X,
        float* __restrict__ out, int finalN) {
    int b = blockIdx.y;
    int n0 = blockIdx.x * 16;
    int N = g_N;
    if (n0 >= N) return;
    int tid = threadIdx.x;
    __shared__ __align__(16) float sHT[512][16];
    const float4* H4 = (const float4*)H;
    for (int v = tid; v < 16*128; v += 128) {
        int p = v & 15, kq = v >> 4;
        int n = n0 + p;
        float4 h4 = (n < N) ? H4[((size_t)b*MAXN + n)*128 + kq]
                            : make_float4(0.f, 0.f, 0.f, 0.f);
        sHT[4*kq+0][p] = h4.x; sHT[4*kq+1][p] = h4.y;
        sHT[4*kq+2][p] = h4.z; sHT[4*kq+3][p] = h4.w;
    }
    __syncthreads();
    float bs = bias[tid];
    ull acc2[8];
    ull bini = pack2(bs, bs);
    #pragma unroll
    for (int j = 0; j < 8; j++) acc2[j] = bini;
    #pragma unroll 4
    for (int k = 0; k < 512; k++) {
        float w = W[k*128 + tid];
        ull w2 = pack2(w, w);
        const ulonglong2* yr = (const ulonglong2*)&sHT[k][0];
        ulonglong2 y0 = yr[0], y1 = yr[1], y2 = yr[2], y3 = yr[3];
        acc2[0] = fma2(w2, y0.x, acc2[0]); acc2[1] = fma2(w2, y0.y, acc2[1]);
        acc2[2] = fma2(w2, y1.x, acc2[2]); acc2[3] = fma2(w2, y1.y, acc2[3]);
        acc2[4] = fma2(w2, y2.x, acc2[4]); acc2[5] = fma2(w2, y2.y, acc2[5]);
        acc2[6] = fma2(w2, y3.x, acc2[6]); acc2[7] = fma2(w2, y3.y, acc2[7]);
    }
    #pragma unroll
    for (int j = 0; j < 8; j++) {
        float2 u = unpack2(acc2[j]);
        int n = n0 + 2*j;
        if (n < N)
            out[((size_t)b*finalN + n)*C + tid] =
                X[((size_t)b*MAXN + n)*C + tid] + u.x;
        if (n + 1 < N)
            out[((size_t)b*finalN + n + 1)*C + tid] =
                X[((size_t)b*MAXN + n + 1)*C + tid] + u.y;
    }
}

// ---------------- host orchestration ----------------------------------------
extern "C" void kernel_launch(void* const* d_in, const int* in_sizes, int n_in,
                              void* d_out, int out_size) {
    const float* conv_w   = (const float*)d_in[0];
    const float* conv_b   = (const float*)d_in[1];
    const float* cls_tok  = (const float*)d_in[2];
    const float* pos      = (const float*)d_in[3];
    const float* ln1_w    = (const float*)d_in[4];
    const float* ln1_b    = (const float*)d_in[5];
    const float* qkv_w    = (const float*)d_in[6];
    const float* qkv_b    = (const float*)d_in[7];
    const float* out_w    = (const float*)d_in[8];
    const float* out_b    = (const float*)d_in[9];
    const float* ln2_w    = (const float*)d_in[10];
    const float* ln2_b    = (const float*)d_in[11];
    const float* mlp_w1   = (const float*)d_in[12];
    const float* mlp_b1   = (const float*)d_in[13];
    const float* mlp_w2   = (const float*)d_in[14];
    const float* mlp_b2   = (const float*)d_in[15];
    const float* x        = (const float*)d_in[16];
    float* out = (float*)d_out;

    float *pX0, *pX1, *pQ, *pK, *pV, *pO, *pH;
    cudaGetSymbolAddress((void**)&pX0, g_X0);
    cudaGetSymbolAddress((void**)&pX1, g_X1);
    cudaGetSymbolAddress((void**)&pQ,  g_Q);
    cudaGetSymbolAddress((void**)&pK,  g_K);
    cudaGetSymbolAddress((void**)&pV,  g_V);
    cudaGetSymbolAddress((void**)&pO,  g_O);
    cudaGetSymbolAddress((void**)&pH,  g_H);

    const float THRESH[3] = {0.001f, 0.0012f, 0.0015f};
    int finalN = out_size / (BATCH * C);

    k_transpose<<<768, 128>>>(conv_w);
    k_patchQKV<<<dim3(65, BATCH), 128>>>(x, conv_b, cls_tok, pos, pX0,
                                         ln1_w, ln1_b, qkv_w, qkv_b,
                                         pQ, pK, pV);

    float* cur = pX0;
    float* alt = pX1;
    dim3 gBlk(65, BATCH);
    dim3 gAtt((MAXN + 63)/64, BATCH*NH);

    for (int i = 0; i < L; i++) {
        k_attn8<<<gAtt, 128>>>(pQ, pK, pV, pO);
        if (i < L - 1) {
            k_prune1<<<BATCH, 1024>>>(THRESH[i], i);
            k_pf1G<<<gBlk, 128>>>(pO, out_w + (size_t)i*C*C, out_b + i*C, cur,
                                  ln2_w + i*C, ln2_b + i*C,
                                  mlp_w1 + (size_t)i*C*512, mlp_b1 + i*512,
                                  pH, i);
            k_fc2G<<<gBlk, 128>>>(pH, mlp_w2 + (size_t)i*512*C, mlp_b2 + i*C,
                                  cur, alt, pos, i);
            k_qkvln<<<gBlk, 128>>>(alt, ln1_w + (i+1)*C, ln1_b + (i+1)*C,
                                   qkv_w + (size_t)(i+1)*C*384,
                                   qkv_b + (i+1)*384, pQ, pK, pV);
            float* tmp = cur; cur = alt; alt = tmp;
        } else {
            k_pf1D<<<gBlk, 128>>>(pO, out_w + (size_t)i*C*C, out_b + i*C, cur,
                                  ln2_w + i*C, ln2_b + i*C,
                                  mlp_w1 + (size_t)i*C*512, mlp_b1 + i*512, pH);
            k_fc2D<<<gBlk, 128>>>(pH, mlp_w2 + (size_t)i*512*C, mlp_b2 + i*C,
                                  cur, out, finalN);
        }
    }
}

// round 15
// speedup vs baseline: 1.0325x; 1.0325x over previous
#include <cuda_runtime.h>
#include <math.h>

#define MAXN 1025
#define BATCH 8
#define C 128
#define NH 8
#define HD 16
#define L 4
#define TKA 128

typedef unsigned long long ull;

// ---------------- packed fp32x2 helpers (sm_103a FFMA2 path) ---------------
__device__ __forceinline__ ull pack2(float lo, float hi) {
    ull r; asm("mov.b64 %0, {%1, %2};" : "=l"(r) : "f"(lo), "f"(hi)); return r;
}
__device__ __forceinline__ float2 unpack2(ull v) {
    float lo, hi; asm("mov.b64 {%0, %1}, %2;" : "=f"(lo), "=f"(hi) : "l"(v));
    return make_float2(lo, hi);
}
__device__ __forceinline__ ull fma2(ull a, ull b, ull c) {
    ull d; asm("fma.rn.f32x2 %0, %1, %2, %3;" : "=l"(d) : "l"(a), "l"(b), "l"(c));
    return d;
}
__device__ __forceinline__ ull mul2(ull a, ull b) {
    ull d; asm("mul.rn.f32x2 %0, %1, %2;" : "=l"(d) : "l"(a), "l"(b));
    return d;
}
__device__ __forceinline__ ull add2(ull a, ull b) {
    ull d; asm("add.rn.f32x2 %0, %1, %2;" : "=l"(d) : "l"(a), "l"(b));
    return d;
}

// ---------------- cp.async helper -------------------------------------------
__device__ __forceinline__ void cp_async16(unsigned saddr, const void* gaddr) {
    asm volatile("cp.async.ca.shared.global [%0], [%1], 16;"
                 :: "r"(saddr), "l"(gaddr));
}
#define CP_COMMIT() asm volatile("cp.async.commit_group;" ::: "memory")
#define CP_WAIT(n)  asm volatile("cp.async.wait_group %0;" :: "n"(n) : "memory")

// ---------------- device scratch (static, allocation-free) ----------------
__device__ float g_X0[BATCH*MAXN*C];
__device__ float g_X1[BATCH*MAXN*C];
__device__ float g_Q [BATCH*NH*MAXN*HD];
__device__ float g_K [BATCH*NH*MAXN*HD];
__device__ float g_V [BATCH*NH*MAXN*HD];
__device__ float g_O [BATCH*MAXN*C];
__device__ float g_H [BATCH*MAXN*512];
__device__ float g_CLSP[BATCH*NH*MAXN];
__device__ float g_WT[768*128];
__device__ int   g_order[BATCH][1024];
__device__ int   g_count[BATCH];
__device__ int   g_mk[3];
__device__ int   g_N;
__device__ int   g_done;

// transpose conv_w (128,768) -> (768,128); also does global init
__global__ void k_transpose(const float* __restrict__ w) {
    int k = blockIdx.x, c = threadIdx.x;
    g_WT[k*128 + c] = w[c*768 + k];
    if (k == 0 && c == 0) {
        g_N = MAXN;
        g_mk[0] = 0; g_mk[1] = 0; g_mk[2] = 0;
        g_done = 0;
    }
}

// ---------------- patch embed + cls row ------------------------------------
__global__ void __launch_bounds__(128) k_patch(
        const float* __restrict__ x, const float* __restrict__ cb,
        const float* __restrict__ cls, const float* __restrict__ pos,
        float* __restrict__ X) {
    int b = blockIdx.y;
    int tid = threadIdx.x;
    if (blockIdx.x == 64) {
        X[(size_t)b*MAXN*C + tid] = cls[tid] + pos[tid];
        return;
    }
    int t0 = blockIdx.x * 16;
    __shared__ __align__(16) float sPT[768][16];
    for (int v = tid; v < 768*16; v += 128) {
        int p = v & 15, k = v >> 4;
        int t = t0 + p;
        int ph = t >> 5, pw = t & 31;
        int ch = k >> 8, rem = k & 255, py = rem >> 4, px = rem & 15;
        sPT[k][p] = x[((size_t)(b*3 + ch)*512 + ph*16 + py)*512 + pw*16 + px];
    }
    __syncthreads();
    float bias = cb[tid];
    ull acc2[8];
    ull bini = pack2(bias, bias);
    #pragma unroll
    for (int j = 0; j < 8; j++) acc2[j] = bini;
    #pragma unroll 4
    for (int k = 0; k < 768; k++) {
        float w = g_WT[k*128 + tid];
        ull w2 = pack2(w, w);
        const ulonglong2* yr = (const ulonglong2*)&sPT[k][0];
        ulonglong2 y0 = yr[0], y1 = yr[1], y2 = yr[2], y3 = yr[3];
        acc2[0] = fma2(w2, y0.x, acc2[0]); acc2[1] = fma2(w2, y0.y, acc2[1]);
        acc2[2] = fma2(w2, y1.x, acc2[2]); acc2[3] = fma2(w2, y1.y, acc2[3]);
        acc2[4] = fma2(w2, y2.x, acc2[4]); acc2[5] = fma2(w2, y2.y, acc2[5]);
        acc2[6] = fma2(w2, y3.x, acc2[6]); acc2[7] = fma2(w2, y3.y, acc2[7]);
    }
    #pragma unroll
    for (int j = 0; j < 8; j++) {
        float2 u = unpack2(acc2[j]);
        int t = t0 + 2*j;
        X[((size_t)b*MAXN + 1 + t)*C + tid]     = u.x + pos[(1 + t)*C + tid];
        X[((size_t)b*MAXN + 2 + t)*C + tid]     = u.y + pos[(2 + t)*C + tid];
    }
}

// ---------------- LN helper (16 tokens, 128 threads) -----------------------
#define LN16_BODY(lwp, lbp)                                                     \
    {                                                                           \
        _Pragma("unroll")                                                       \
        for (int p = 0; p < 16; p++) {                                          \
            float s = xv[p];                                                    \
            _Pragma("unroll")                                                   \
            for (int o = 16; o; o >>= 1) s += __shfl_xor_sync(~0u, s, o);       \
            if (!lane) sRed[0][wid][p] = s;                                     \
        }                                                                       \
        __syncthreads();                                                        \
        _Pragma("unroll")                                                       \
        for (int p = 0; p < 16; p++) {                                          \
            float mu = (sRed[0][0][p] + sRed[0][1][p] + sRed[0][2][p]           \
                        + sRed[0][3][p]) * 0.0078125f;                          \
            float d = xv[p] - mu; xv[p] = d;                                    \
            float s = d * d;                                                    \
            _Pragma("unroll")                                                   \
            for (int o = 16; o; o >>= 1) s += __shfl_xor_sync(~0u, s, o);       \
            if (!lane) sRed[1][wid][p] = s;                                     \
        }                                                                       \
        __syncthreads();                                                        \
        float wgt = (lwp)[tid], bia = (lbp)[tid];                               \
        _Pragma("unroll")                                                       \
        for (int p4 = 0; p4 < 4; p4++) {                                        \
            float4 pk;                                                          \
            float* pkf = (float*)&pk;                                           \
            _Pragma("unroll")                                                   \
            for (int j = 0; j < 4; j++) {                                       \
                int p = 4*p4 + j;                                               \
                float var = (sRed[1][0][p] + sRed[1][1][p] + sRed[1][2][p]      \
                             + sRed[1][3][p]) * 0.0078125f;                     \
                pkf[j] = xv[p] * rsqrtf(var + 1e-5f) * wgt + bia;               \
            }                                                                   \
            sYT[tid][p4] = pk;                                                  \
        }                                                                       \
        __syncthreads();                                                        \
    }

// slot -> src gather table (16 slots per CTA); slot 0 = CLS
#define GATHER_SETUP(pi)                                                        \
    int mk1 = 1 + g_mk[pi];                                                     \
    if (s0 >= mk1) return;                                                      \
    int tid = threadIdx.x;                                                      \
    __shared__ int sSrc[16];                                                    \
    __shared__ int sVal[16];                                                    \
    if (tid < 16) {                                                             \
        int slot = s0 + tid;                                                    \
        int valid = 0, src = 0;                                                 \
        if (slot == 0) { valid = 1; src = 0; }                                  \
        else if (slot < mk1 && slot - 1 < g_count[b]) {                         \
            valid = 1; src = 1 + g_order[b][slot - 1];                          \
        }                                                                       \
        sSrc[tid] = src; sVal[tid] = valid;                                     \
    }

// ---------------- LN + qkv -> head-major Q,K,V [b,h,n,16] ------------------
__global__ void __launch_bounds__(128) k_qkvln(
        const float* __restrict__ X, const float* __restrict__ lw,
        const float* __restrict__ lb, const float* __restrict__ W,
        const float* __restrict__ bias,
        float* __restrict__ Qo, float* __restrict__ Ko, float* __restrict__ Vo) {
    int b = blockIdx.y;
    int n0 = blockIdx.x * 16;
    int N = g_N;
    if (n0 >= N) return;
    int tid = threadIdx.x, wid = tid >> 5, lane = tid & 31;
    __shared__ float4 sYT[128][4];
    __shared__ float sRed[2][4][16];
    float xv[16];
    #pragma unroll
    for (int p = 0; p < 16; p++) {
        int n = n0 + p;
        xv[p] = (n < N) ? X[((size_t)b*MAXN + n)*C + tid] : 0.0f;
    }
    LN16_BODY(lw, lb)
    float b0 = bias[tid], b1 = bias[tid + 128], b2 = bias[tid + 256];
    ull a0[8], a1[8], a2[8];
    ull i0 = pack2(b0, b0), i1 = pack2(b1, b1), i2 = pack2(b2, b2);
    #pragma unroll
    for (int j = 0; j < 8; j++) { a0[j] = i0; a1[j] = i1; a2[j] = i2; }
    #pragma unroll 4
    for (int k = 0; k < 128; k++) {
        float w0 = W[k*384 + tid];
        float w1 = W[k*384 + 128 + tid];
        float w2 = W[k*384 + 256 + tid];
        ull w02 = pack2(w0, w0), w12 = pack2(w1, w1), w22 = pack2(w2, w2);
        const ulonglong2* yr = (const ulonglong2*)&sYT[k][0];
        ulonglong2 y0 = yr[0], y1 = yr[1], y2 = yr[2], y3 = yr[3];
        ull yv[8] = {y0.x, y0.y, y1.x, y1.y, y2.x, y2.y, y3.x, y3.y};
        #pragma unroll
        for (int j = 0; j < 8; j++) {
            a0[j] = fma2(w02, yv[j], a0[j]);
            a1[j] = fma2(w12, yv[j], a1[j]);
            a2[j] = fma2(w22, yv[j], a2[j]);
        }
    }
    int h = tid >> 4, d = tid & 15;
    size_t hb = (size_t)(b*NH + h)*MAXN;
    #pragma unroll
    for (int j = 0; j < 8; j++) {
        float2 q2 = unpack2(a0[j]);
        float2 k2 = unpack2(a1[j]);
        float2 v2 = unpack2(a2[j]);
        int n = n0 + 2*j;
        if (n < N) {
            size_t o = (hb + n)*HD + d;
            Qo[o] = q2.x; Ko[o] = k2.x; Vo[o] = v2.x;
        }
        if (n + 1 < N) {
            size_t o = (hb + n + 1)*HD + d;
            Qo[o] = q2.y; Ko[o] = k2.y; Vo[o] = v2.y;
        }
    }
}

// ---------------- attention v8: split-K + cp.async double buffering ---------
__global__ void __launch_bounds__(128) k_attn8(
        const float* __restrict__ Q, const float* __restrict__ K,
        const float* __restrict__ V, float* __restrict__ O) {
    int N = g_N;
    int bh = blockIdx.y;
    int b = bh >> 3, h = bh & 7;
    int q0 = blockIdx.x * 64;
    if (q0 >= N) return;
    int tid = threadIdx.x, w = tid >> 5, lane = tid & 31;

    __shared__ __align__(16) float sMem[8192];
    unsigned sBase = (unsigned)__cvta_generic_to_shared(sMem);

    const float4* K4 = (const float4*)(K + (size_t)bh*MAXN*HD);
    const float4* V4 = (const float4*)(V + (size_t)bh*MAXN*HD);
    int qA = q0 + lane;
    int qB = q0 + 32 + lane;
    bool vA = qA < N, vB = qB < N;

    ull qa[8], qb[8];
    ull qs = pack2(0.25f, 0.25f);
    #pragma unroll
    for (int j = 0; j < 8; j++) { qa[j] = 0ull; qb[j] = 0ull; }
    if (vA) {
        const float4* Q4 = (const float4*)(Q + ((size_t)bh*MAXN + qA)*HD);
        #pragma unroll
        for (int j = 0; j < 4; j++) {
            float4 t = Q4[j];
            qa[2*j]   = mul2(pack2(t.x, t.y), qs);
            qa[2*j+1] = mul2(pack2(t.z, t.w), qs);
        }
    }
    if (vB) {
        const float4* Q4 = (const float4*)(Q + ((size_t)bh*MAXN + qB)*HD);
        #pragma unroll
        for (int j = 0; j < 4; j++) {
            float4 t = Q4[j];
            qb[2*j]   = mul2(pack2(t.x, t.y), qs);
            qb[2*j+1] = mul2(pack2(t.z, t.w), qs);
        }
    }

    float lA = 0.0f, lB = 0.0f;
    ull accA[8], accB[8];
    #pragma unroll
    for (int j = 0; j < 8; j++) { accA[j] = 0ull; accB[j] = 0ull; }

    int nt = (N + TKA - 1) / TKA;

    {
        int kn0 = min(TKA, N);
        int lim = kn0 * 4;
        for (int i = tid; i < lim; i += 128) {
            unsigned dk = sBase + ((unsigned)i << 4);
            unsigned dv = dk + 8192u;
            cp_async16(dk, K4 + i);
            cp_async16(dv, V4 + i);
        }
        CP_COMMIT();
    }

    for (int t = 0; t < nt; t++) {
        int cur = t & 1;
        if (t + 1 < nt) {
            int nb = (t + 1) * TKA;
            int knn = min(TKA, N - nb);
            int lim = knn * 4;
            unsigned so = sBase + (unsigned)((cur ^ 1) * 16384);
            const float4* gk = K4 + nb*4;
            const float4* gv = V4 + nb*4;
            for (int i = tid; i < lim; i += 128) {
                unsigned dk = so + ((unsigned)i << 4);
                unsigned dv = dk + 8192u;
                cp_async16(dk, gk + i);
                cp_async16(dv, gv + i);
            }
            CP_COMMIT();
            CP_WAIT(1);
        } else {
            CP_WAIT(0);
        }
        __syncthreads();

        int base = t * TKA;
        int kn = min(TKA, N - base);
        const float4* sK = (const float4*)(sMem + cur*4096);
        const float4* sV = (const float4*)(sMem + cur*4096 + 2048);
        int lo = w * 32;
        int hi = min(kn, lo + 32);
        #pragma unroll 2
        for (int m = lo; m < hi; m++) {
            const ulonglong2* kp = (const ulonglong2*)&sK[m*4];
            ulonglong2 k0 = kp[0], k1 = kp[1], k2 = kp[2], k3 = kp[3];
            ull sa = fma2(qa[1], k0.y, mul2(qa[0], k0.x));
            ull sb = fma2(qa[3], k1.y, mul2(qa[2], k1.x));
            ull sc = fma2(qa[5], k2.y, mul2(qa[4], k2.x));
            ull sd = fma2(qa[7], k3.y, mul2(qa[6], k3.x));
            ull stA = add2(add2(sa, sb), add2(sc, sd));
            ull ta = fma2(qb[1], k0.y, mul2(qb[0], k0.x));
            ull tb = fma2(qb[3], k1.y, mul2(qb[2], k1.x));
            ull tc = fma2(qb[5], k2.y, mul2(qb[4], k2.x));
            ull td = fma2(qb[7], k3.y, mul2(qb[6], k3.x));
            ull stB = add2(add2(ta, tb), add2(tc, td));
            float2 spA = unpack2(stA);
            float2 spB = unpack2(stB);
            float eA = __expf(spA.x + spA.y);
            float eB = __expf(spB.x + spB.y);
            lA += eA; lB += eB;
            ull eA2 = pack2(eA, eA);
            ull eB2 = pack2(eB, eB);
            const ulonglong2* vp = (const ulonglong2*)&sV[m*4];
            ulonglong2 v0 = vp[0], v1 = vp[1], v2 = vp[2], v3 = vp[3];
            accA[0] = fma2(eA2, v0.x, accA[0]); accB[0] = fma2(eB2, v0.x, accB[0]);
            accA[1] = fma2(eA2, v0.y, accA[1]); accB[1] = fma2(eB2, v0.y, accB[1]);
            accA[2] = fma2(eA2, v1.x, accA[2]); accB[2] = fma2(eB2, v1.x, accB[2]);
            accA[3] = fma2(eA2, v1.y, accA[3]); accB[3] = fma2(eB2, v1.y, accB[3]);
            accA[4] = fma2(eA2, v2.x, accA[4]); accB[4] = fma2(eB2, v2.x, accB[4]);
            accA[5] = fma2(eA2, v2.y, accA[5]); accB[5] = fma2(eB2, v2.y, accB[5]);
            accA[6] = fma2(eA2, v3.x, accA[6]); accB[6] = fma2(eB2, v3.x, accB[6]);
            accA[7] = fma2(eA2, v3.y, accA[7]); accB[7] = fma2(eB2, v3.y, accB[7]);
        }
        __syncthreads();
    }

    float (*sAcc)[64][17] = (float (*)[64][17])sMem;

    #pragma unroll
    for (int j = 0; j < 8; j++) {
        float2 uA = unpack2(accA[j]);
        float2 uB = unpack2(accB[j]);
        sAcc[w][lane][2*j]      = uA.x;
        sAcc[w][lane][2*j+1]    = uA.y;
        sAcc[w][32+lane][2*j]   = uB.x;
        sAcc[w][32+lane][2*j+1] = uB.y;
    }
    sAcc[w][lane][16]    = lA;
    sAcc[w][32+lane][16] = lB;
    __syncthreads();

    int j = tid >> 1, half = tid & 1;
    int q = q0 + j;
    if (q < N) {
        float lsum = (sAcc[0][j][16] + sAcc[1][j][16])
                   + (sAcc[2][j][16] + sAcc[3][j][16]);
        float inv = 1.0f / lsum;
        int d0 = half * 8;
        float o[8];
        #pragma unroll
        for (int d = 0; d < 8; d++) {
            o[d] = ((sAcc[0][j][d0+d] + sAcc[1][j][d0+d])
                  + (sAcc[2][j][d0+d] + sAcc[3][j][d0+d])) * inv;
        }
        float* op = O + ((size_t)b*MAXN + q)*C + h*HD + d0;
        ((float4*)op)[0] = make_float4(o[0], o[1], o[2], o[3]);
        ((float4*)op)[1] = make_float4(o[4], o[5], o[6], o[7]);
        if (!half) {
            const float4* Q4 = (const float4*)(Q + ((size_t)bh*MAXN + q)*HD);
            float qv[16];
            #pragma unroll
            for (int i = 0; i < 4; i++) {
                float4 tq = Q4[i];
                qv[4*i]   = tq.x * 0.25f; qv[4*i+1] = tq.y * 0.25f;
                qv[4*i+2] = tq.z * 0.25f; qv[4*i+3] = tq.w * 0.25f;
            }
            const float* k0 = K + (size_t)bh*MAXN*HD;
            float sa_l = fmaf(qv[2],  k0[2],  qv[0]*k0[0]);
            float sa_h = fmaf(qv[3],  k0[3],  qv[1]*k0[1]);
            float sb_l = fmaf(qv[6],  k0[6],  qv[4]*k0[4]);
            float sb_h = fmaf(qv[7],  k0[7],  qv[5]*k0[5]);
            float sc_l = fmaf(qv[10], k0[10], qv[8]*k0[8]);
            float sc_h = fmaf(qv[11], k0[11], qv[9]*k0[9]);
            float sd_l = fmaf(qv[14], k0[14], qv[12]*k0[12]);
            float sd_h = fmaf(qv[15], k0[15], qv[13]*k0[13]);
            float slo = (sa_l + sb_l) + (sc_l + sd_l);
            float shi = (sa_h + sb_h) + (sc_h + sd_h);
            g_CLSP[(size_t)bh*MAXN + q] = __expf(slo + shi) * inv;
        }
    }
}

// ---------------- prune (warp-shuffle scan/argmax + folded g_N) -------------
__global__ void k_prune1(float thresh, int pi) {
    int b = blockIdx.x;
    int t = threadIdx.x;
    int lane = t & 31, wid = t >> 5;
    int tc = g_N - 1;
    float am = -1e30f;
    int keep = 0;
    if (t < tc) {
        float s = 0.0f;
        #pragma unroll
        for (int h = 0; h < NH; h++) s += g_CLSP[(b*NH + h)*MAXN + 1 + t];
        am = s * 0.125f;
        keep = (am > thresh) ? 1 : 0;
    }
    int sc = keep;
    #pragma unroll
    for (int o = 1; o < 32; o <<= 1) {
        int v = __shfl_up_sync(~0u, sc, o);
        if (lane >= o) sc += v;
    }
    float bv = am; int bi = t;
    #pragma unroll
    for (int o = 16; o; o >>= 1) {
        float ov = __shfl_xor_sync(~0u, bv, o);
        int   oi = __shfl_xor_sync(~0u, bi, o);
        if (ov > bv || (ov == bv && oi < bi)) { bv = ov; bi = oi; }
    }
    __shared__ int wsum[32], wbi[32], woff[32];
    __shared__ float wbv[32];
    __shared__ int gArg, gTot;
    if (lane == 31) wsum[wid] = sc;
    if (lane == 0) { wbv[wid] = bv; wbi[wid] = bi; }
    __syncthreads();
    if (wid == 0) {
        int v = wsum[lane];
        int s2 = v;
        #pragma unroll
        for (int o = 1; o < 32; o <<= 1) {
            int u = __shfl_up_sync(~0u, s2, o);
            if (lane >= o) s2 += u;
        }
        woff[lane] = s2 - v;
        if (lane == 31) gTot = s2;
        float bv2 = wbv[lane]; int bi2 = wbi[lane];
        #pragma unroll
        for (int o = 16; o; o >>= 1) {
            float ov = __shfl_xor_sync(~0u, bv2, o);
            int   oi = __shfl_xor_sync(~0u, bi2, o);
            if (ov > bv2 || (ov == bv2 && oi < bi2)) { bv2 = ov; bi2 = oi; }
        }
        if (lane == 0) gArg = bi2;
    }
    __syncthreads();
    int total = gTot;
    int posi = woff[wid] + sc;
    if (total > 0 && keep) g_order[b][posi - 1] = t;
    if (t == 0) {
        int cnt = total;
        if (total == 0) { g_order[b][0] = gArg; cnt = 1; }
        g_count[b] = cnt;
        atomicMax(&g_mk[pi], cnt);
        __threadfence();
        int tk = atomicAdd(&g_done, 1);
        if (tk == BATCH - 1) {
            g_N = 1 + g_mk[pi];
            g_done = 0;
        }
    }
}

// ---------- fused gathered proj + LN2 + fc1 + gelu (layers 0-2) -------------
__global__ void __launch_bounds__(128) k_pf1G(
        const float* __restrict__ Oin, const float* __restrict__ Wp,
        const float* __restrict__ bp, float* __restrict__ X,
        const float* __restrict__ lw, const float* __restrict__ lb,
        const float* __restrict__ W1, const float* __restrict__ b1,
        float* __restrict__ H, int pi) {
    int b = blockIdx.y;
    int s0 = blockIdx.x * 16;
    GATHER_SETUP(pi)
    int wid = tid >> 5, lane = tid & 31;
    __shared__ __align__(16) float sOT[128][16];
    __shared__ float4 sYT[128][4];
    __shared__ float sRed[2][4][16];
    __syncthreads();
    const float4* O4 = (const float4*)Oin;
    for (int v = tid; v < 16*32; v += 128) {
        int p = v & 15, kq = v >> 4;
        float4 o4 = sVal[p] ? O4[((size_t)b*MAXN + sSrc[p])*32 + kq]
                            : make_float4(0.f, 0.f, 0.f, 0.f);
        sOT[4*kq+0][p] = o4.x; sOT[4*kq+1][p] = o4.y;
        sOT[4*kq+2][p] = o4.z; sOT[4*kq+3][p] = o4.w;
    }
    __syncthreads();
    float bs = bp[tid];
    ull acc2[8];
    ull bini = pack2(bs, bs);
    #pragma unroll
    for (int j = 0; j < 8; j++) acc2[j] = bini;
    #pragma unroll 4
    for (int k = 0; k < 128; k++) {
        float w = Wp[k*128 + tid];
        ull w2 = pack2(w, w);
        const ulonglong2* yr = (const ulonglong2*)&sOT[k][0];
        ulonglong2 y0 = yr[0], y1 = yr[1], y2 = yr[2], y3 = yr[3];
        acc2[0] = fma2(w2, y0.x, acc2[0]); acc2[1] = fma2(w2, y0.y, acc2[1]);
        acc2[2] = fma2(w2, y1.x, acc2[2]); acc2[3] = fma2(w2, y1.y, acc2[3]);
        acc2[4] = fma2(w2, y2.x, acc2[4]); acc2[5] = fma2(w2, y2.y, acc2[5]);
        acc2[6] = fma2(w2, y3.x, acc2[6]); acc2[7] = fma2(w2, y3.y, acc2[7]);
    }
    float xv[16];
    #pragma unroll
    for (int j = 0; j < 8; j++) {
        float2 u = unpack2(acc2[j]);
        int p0 = 2*j, p1 = 2*j + 1;
        if (sVal[p0]) {
            float t0 = X[((size_t)b*MAXN + sSrc[p0])*C + tid] + u.x;
            X[((size_t)b*MAXN + sSrc[p0])*C + tid] = t0;
            xv[p0] = t0;
        } else xv[p0] = 0.0f;
        if (sVal[p1]) {
            float t1 = X[((size_t)b*MAXN + sSrc[p1])*C + tid] + u.y;
            X[((size_t)b*MAXN + sSrc[p1])*C + tid] = t1;
            xv[p1] = t1;
        } else xv[p1] = 0.0f;
    }
    LN16_BODY(lw, lb)
    const float4* W4 = (const float4*)W1;
    float4 b4 = ((const float4*)b1)[tid];
    ull a0[8], a1[8], a2[8], a3[8];
    ull i0 = pack2(b4.x, b4.x), i1 = pack2(b4.y, b4.y);
    ull i2 = pack2(b4.z, b4.z), i3 = pack2(b4.w, b4.w);
    #pragma unroll
    for (int j = 0; j < 8; j++) { a0[j]=i0; a1[j]=i1; a2[j]=i2; a3[j]=i3; }
    #pragma unroll 2
    for (int k = 0; k < 128; k++) {
        float4 w4 = W4[k*128 + tid];
        ull w0 = pack2(w4.x, w4.x), w1 = pack2(w4.y, w4.y);
        ull w2 = pack2(w4.z, w4.z), w3 = pack2(w4.w, w4.w);
        const ulonglong2* yr = (const ulonglong2*)&sYT[k][0];
        ulonglong2 y0 = yr[0], y1 = yr[1], y2 = yr[2], y3 = yr[3];
        ull yv8[8] = {y0.x, y0.y, y1.x, y1.y, y2.x, y2.y, y3.x, y3.y};
        #pragma unroll
        for (int j = 0; j < 8; j++) {
            a0[j] = fma2(w0, yv8[j], a0[j]);
            a1[j] = fma2(w1, yv8[j], a1[j]);
            a2[j] = fma2(w2, yv8[j], a2[j]);
            a3[j] = fma2(w3, yv8[j], a3[j]);
        }
    }
    float4* H4 = (float4*)H;
    #pragma unroll
    for (int j = 0; j < 8; j++) {
        float2 u0 = unpack2(a0[j]);
        float2 u1 = unpack2(a1[j]);
        float2 u2 = unpack2(a2[j]);
        float2 u3 = unpack2(a3[j]);
        int slot = s0 + 2*j;
        if (slot < mk1) {
            float4 hv;
            hv.x = 0.5f*u0.x*(1.0f + erff(u0.x*0.70710678118654752f));
            hv.y = 0.5f*u1.x*(1.0f + erff(u1.x*0.70710678118654752f));
            hv.z = 0.5f*u2.x*(1.0f + erff(u2.x*0.70710678118654752f));
            hv.w = 0.5f*u3.x*(1.0f + erff(u3.x*0.70710678118654752f));
            H4[((size_t)b*MAXN + slot)*128 + tid] = hv;
        }
        if (slot + 1 < mk1) {
            float4 hv;
            hv.x = 0.5f*u0.y*(1.0f + erff(u0.y*0.70710678118654752f));
            hv.y = 0.5f*u1.y*(1.0f + erff(u1.y*0.70710678118654752f));
            hv.z = 0.5f*u2.y*(1.0f + erff(u2.y*0.70710678118654752f));
            hv.w = 0.5f*u3.y*(1.0f + erff(u3.y*0.70710678118654752f));
            H4[((size_t)b*MAXN + slot + 1)*128 + tid] = hv;
        }
    }
}

// ---------- fused dense proj + LN2 + fc1 + gelu (layer 3) -------------------
__global__ void __launch_bounds__(128) k_pf1D(
        const float* __restrict__ Oin, const float* __restrict__ Wp,
        const float* __restrict__ bp, float* __restrict__ X,
        const float* __restrict__ lw, const float* __restrict__ lb,
        const float* __restrict__ W1, const float* __restrict__ b1,
        float* __restrict__ H) {
    int b = blockIdx.y;
    int n0 = blockIdx.x * 16;
    int N = g_N;
    if (n0 >= N) return;
    int tid = threadIdx.x, wid = tid >> 5, lane = tid & 31;
    __shared__ __align__(16) float sOT[128][16];
    __shared__ float4 sYT[128][4];
    __shared__ float sRed[2][4][16];
    const float4* O4 = (const float4*)Oin;
    for (int v = tid; v < 16*32; v += 128) {
        int p = v & 15, kq = v >> 4;
        int n = n0 + p;
        float4 o4 = (n < N) ? O4[((size_t)b*MAXN + n)*32 + kq]
                            : make_float4(0.f, 0.f, 0.f, 0.f);
        sOT[4*kq+0][p] = o4.x; sOT[4*kq+1][p] = o4.y;
        sOT[4*kq+2][p] = o4.z; sOT[4*kq+3][p] = o4.w;
    }
    __syncthreads();
    float bs = bp[tid];
    ull acc2[8];
    ull bini = pack2(bs, bs);
    #pragma unroll
    for (int j = 0; j < 8; j++) acc2[j] = bini;
    #pragma unroll 4
    for (int k = 0; k < 128; k++) {
        float w = Wp[k*128 + tid];
        ull w2 = pack2(w, w);
        const ulonglong2* yr = (const ulonglong2*)&sOT[k][0];
        ulonglong2 y0 = yr[0], y1 = yr[1], y2 = yr[2], y3 = yr[3];
        acc2[0] = fma2(w2, y0.x, acc2[0]); acc2[1] = fma2(w2, y0.y, acc2[1]);
        acc2[2] = fma2(w2, y1.x, acc2[2]); acc2[3] = fma2(w2, y1.y, acc2[3]);
        acc2[4] = fma2(w2, y2.x, acc2[4]); acc2[5] = fma2(w2, y2.y, acc2[5]);
        acc2[6] = fma2(w2, y3.x, acc2[6]); acc2[7] = fma2(w2, y3.y, acc2[7]);
    }
    float xv[16];
    #pragma unroll
    for (int j = 0; j < 8; j++) {
        float2 u = unpack2(acc2[j]);
        int n = n0 + 2*j;
        if (n < N) {
            float t0 = X[((size_t)b*MAXN + n)*C + tid] + u.x;
            X[((size_t)b*MAXN + n)*C + tid] = t0;
            xv[2*j] = t0;
        } else xv[2*j] = 0.0f;
        if (n + 1 < N) {
            float t1 = X[((size_t)b*MAXN + n + 1)*C + tid] + u.y;
            X[((size_t)b*MAXN + n + 1)*C + tid] = t1;
            xv[2*j+1] = t1;
        } else xv[2*j+1] = 0.0f;
    }
    LN16_BODY(lw, lb)
    const float4* W4 = (const float4*)W1;
    float4 b4 = ((const float4*)b1)[tid];
    ull a0[8], a1[8], a2[8], a3[8];
    ull i0 = pack2(b4.x, b4.x), i1 = pack2(b4.y, b4.y);
    ull i2 = pack2(b4.z, b4.z), i3 = pack2(b4.w, b4.w);
    #pragma unroll
    for (int j = 0; j < 8; j++) { a0[j]=i0; a1[j]=i1; a2[j]=i2; a3[j]=i3; }
    #pragma unroll 2
    for (int k = 0; k < 128; k++) {
        float4 w4 = W4[k*128 + tid];
        ull w0 = pack2(w4.x, w4.x), w1 = pack2(w4.y, w4.y);
        ull w2 = pack2(w4.z, w4.z), w3 = pack2(w4.w, w4.w);
        const ulonglong2* yr = (const ulonglong2*)&sYT[k][0];
        ulonglong2 y0 = yr[0], y1 = yr[1], y2 = yr[2], y3 = yr[3];
        ull yv8[8] = {y0.x, y0.y, y1.x, y1.y, y2.x, y2.y, y3.x, y3.y};
        #pragma unroll
        for (int j = 0; j < 8; j++) {
            a0[j] = fma2(w0, yv8[j], a0[j]);
            a1[j] = fma2(w1, yv8[j], a1[j]);
            a2[j] = fma2(w2, yv8[j], a2[j]);
            a3[j] = fma2(w3, yv8[j], a3[j]);
        }
    }
    float4* H4 = (float4*)H;
    #pragma unroll
    for (int j = 0; j < 8; j++) {
        float2 u0 = unpack2(a0[j]);
        float2 u1 = unpack2(a1[j]);
        float2 u2 = unpack2(a2[j]);
        float2 u3 = unpack2(a3[j]);
        int n = n0 + 2*j;
        if (n < N) {
            float4 hv;
            hv.x = 0.5f*u0.x*(1.0f + erff(u0.x*0.70710678118654752f));
            hv.y = 0.5f*u1.x*(1.0f + erff(u1.x*0.70710678118654752f));
            hv.z = 0.5f*u2.x*(1.0f + erff(u2.x*0.70710678118654752f));
            hv.w = 0.5f*u3.x*(1.0f + erff(u3.x*0.70710678118654752f));
            H4[((size_t)b*MAXN + n)*128 + tid] = hv;
        }
        if (n + 1 < N) {
            float4 hv;
            hv.x = 0.5f*u0.y*(1.0f + erff(u0.y*0.70710678118654752f));
            hv.y = 0.5f*u1.y*(1.0f + erff(u1.y*0.70710678118654752f));
            hv.z = 0.5f*u2.y*(1.0f + erff(u2.y*0.70710678118654752f));
            hv.w = 0.5f*u3.y*(1.0f + erff(u3.y*0.70710678118654752f));
            H4[((size_t)b*MAXN + n + 1)*128 + tid] = hv;
        }
    }
}

// ---------------- gathered fc2 (layers 0-2): compact + residual + pos -------
__global__ void __launch_bounds__(128) k_fc2G(
        const float* __restrict__ H, const float* __restrict__ W,
        const float* __restrict__ bias, const float* __restrict__ Xold,
        float* __restrict__ Xnew, const float* __restrict__ pos, int pi) {
    int b = blockIdx.y;
    int s0 = blockIdx.x * 16;
    GATHER_SETUP(pi)
    __shared__ __align__(16) float sHT[512][16];
    __syncthreads();
    const float4* H4 = (const float4*)H;
    for (int v = tid; v < 16*128; v += 128) {
        int p = v & 15, kq = v >> 4;
        int slot = s0 + p;
        float4 h4 = (slot < mk1) ? H4[((size_t)b*MAXN + slot)*128 + kq]
                                 : make_float4(0.f, 0.f, 0.f, 0.f);
        sHT[4*kq+0][p] = h4.x; sHT[4*kq+1][p] = h4.y;
        sHT[4*kq+2][p] = h4.z; sHT[4*kq+3][p] = h4.w;
    }
    __syncthreads();
    float bs = bias[tid];
    ull acc2[8];
    ull bini = pack2(bs, bs);
    #pragma unroll
    for (int j = 0; j < 8; j++) acc2[j] = bini;
    #pragma unroll 4
    for (int k = 0; k < 512; k++) {
        float w = W[k*128 + tid];
        ull w2 = pack2(w, w);
        const ulonglong2* yr = (const ulonglong2*)&sHT[k][0];
        ulonglong2 y0 = yr[0], y1 = yr[1], y2 = yr[2], y3 = yr[3];
        acc2[0] = fma2(w2, y0.x, acc2[0]); acc2[1] = fma2(w2, y0.y, acc2[1]);
        acc2[2] = fma2(w2, y1.x, acc2[2]); acc2[3] = fma2(w2, y1.y, acc2[3]);
        acc2[4] = fma2(w2, y2.x, acc2[4]); acc2[5] = fma2(w2, y2.y, acc2[5]);
        acc2[6] = fma2(w2, y3.x, acc2[6]); acc2[7] = fma2(w2, y3.y, acc2[7]);
    }
    #pragma unroll
    for (int j = 0; j < 8; j++) {
        float2 u = unpack2(acc2[j]);
        int p0 = 2*j, p1 = 2*j + 1;
        int slot0 = s0 + p0, slot1 = s0 + p1;
        if (slot0 < mk1) {
            float base = sVal[p0]
                ? Xold[((size_t)b*MAXN + sSrc[p0])*C + tid] + u.x : 0.0f;
            Xnew[((size_t)b*MAXN + slot0)*C + tid] = base + pos[slot0*C + tid];
        }
        if (slot1 < mk1) {
            float base = sVal[p1]
                ? Xold[((size_t)b*MAXN + sSrc[p1])*C + tid] + u.y : 0.0f;
            Xnew[((size_t)b*MAXN + slot1)*C + tid] = base + pos[slot1*C + tid];
        }
    }
}

// ---------------- dense fc2 (layer 3): writes residual sum to out -----------
__global__ void __launch_bounds__(128) k_fc2D(
        const float* __restrict__ H, const float* __restrict__ W,
        const float* __restrict__ bias, const float* __restrict__ X,
        float* __restrict__ out, int finalN) {
    int b = blockIdx.y;
    int n0 = blockIdx.x * 16;
    int N = g_N;
    if (n0 >= N) return;
    int tid = threadIdx.x;
    __shared__ __align__(16) float sHT[512][16];
    const float4* H4 = (const float4*)H;
    for (int v = tid; v < 16*128; v += 128) {
        int p = v & 15, kq = v >> 4;
        int n = n0 + p;
        float4 h4 = (n < N) ? H4[((size_t)b*MAXN + n)*128 + kq]
                            : make_float4(0.f, 0.f, 0.f, 0.f);
        sHT[4*kq+0][p] = h4.x; sHT[4*kq+1][p] = h4.y;
        sHT[4*kq+2][p] = h4.z; sHT[4*kq+3][p] = h4.w;
    }
    __syncthreads();
    float bs = bias[tid];
    ull acc2[8];
    ull bini = pack2(bs, bs);
    #pragma unroll
    for (int j = 0; j < 8; j++) acc2[j] = bini;
    #pragma unroll 4
    for (int k = 0; k < 512; k++) {
        float w = W[k*128 + tid];
        ull w2 = pack2(w, w);
        const ulonglong2* yr = (const ulonglong2*)&sHT[k][0];
        ulonglong2 y0 = yr[0], y1 = yr[1], y2 = yr[2], y3 = yr[3];
        acc2[0] = fma2(w2, y0.x, acc2[0]); acc2[1] = fma2(w2, y0.y, acc2[1]);
        acc2[2] = fma2(w2, y1.x, acc2[2]); acc2[3] = fma2(w2, y1.y, acc2[3]);
        acc2[4] = fma2(w2, y2.x, acc2[4]); acc2[5] = fma2(w2, y2.y, acc2[5]);
        acc2[6] = fma2(w2, y3.x, acc2[6]); acc2[7] = fma2(w2, y3.y, acc2[7]);
    }
    #pragma unroll
    for (int j = 0; j < 8; j++) {
        float2 u = unpack2(acc2[j]);
        int n = n0 + 2*j;
        if (n < N)
            out[((size_t)b*finalN + n)*C + tid] =
                X[((size_t)b*MAXN + n)*C + tid] + u.x;
        if (n + 1 < N)
            out[((size_t)b*finalN + n + 1)*C + tid] =
                X[((size_t)b*MAXN + n + 1)*C + tid] + u.y;
    }
}

// ---------------- host orchestration ----------------------------------------
extern "C" void kernel_launch(void* const* d_in, const int* in_sizes, int n_in,
                              void* d_out, int out_size) {
    const float* conv_w   = (const float*)d_in[0];
    const float* conv_b   = (const float*)d_in[1];
    const float* cls_tok  = (const float*)d_in[2];
    const float* pos      = (const float*)d_in[3];
    const float* ln1_w    = (const float*)d_in[4];
    const float* ln1_b    = (const float*)d_in[5];
    const float* qkv_w    = (const float*)d_in[6];
    const float* qkv_b    = (const float*)d_in[7];
    const float* out_w    = (const float*)d_in[8];
    const float* out_b    = (const float*)d_in[9];
    const float* ln2_w    = (const float*)d_in[10];
    const float* ln2_b    = (const float*)d_in[11];
    const float* mlp_w1   = (const float*)d_in[12];
    const float* mlp_b1   = (const float*)d_in[13];
    const float* mlp_w2   = (const float*)d_in[14];
    const float* mlp_b2   = (const float*)d_in[15];
    const float* x        = (const float*)d_in[16];
    float* out = (float*)d_out;

    float *pX0, *pX1, *pQ, *pK, *pV, *pO, *pH;
    cudaGetSymbolAddress((void**)&pX0, g_X0);
    cudaGetSymbolAddress((void**)&pX1, g_X1);
    cudaGetSymbolAddress((void**)&pQ,  g_Q);
    cudaGetSymbolAddress((void**)&pK,  g_K);
    cudaGetSymbolAddress((void**)&pV,  g_V);
    cudaGetSymbolAddress((void**)&pO,  g_O);
    cudaGetSymbolAddress((void**)&pH,  g_H);

    const float THRESH[3] = {0.001f, 0.0012f, 0.0015f};
    int finalN = out_size / (BATCH * C);

    k_transpose<<<768, 128>>>(conv_w);
    k_patch<<<dim3(65, BATCH), 128>>>(x, conv_b, cls_tok, pos, pX0);

    float* cur = pX0;
    float* alt = pX1;
    dim3 gBlk(65, BATCH);
    dim3 gAtt((MAXN + 63)/64, BATCH*NH);

    for (int i = 0; i < L; i++) {
        k_qkvln<<<gBlk, 128>>>(cur, ln1_w + i*C, ln1_b + i*C,
                               qkv_w + (size_t)i*C*384, qkv_b + i*384, pQ, pK, pV);
        k_attn8<<<gAtt, 128>>>(pQ, pK, pV, pO);
        if (i < L - 1) {
            k_prune1<<<BATCH, 1024>>>(THRESH[i], i);
            k_pf1G<<<gBlk, 128>>>(pO, out_w + (size_t)i*C*C, out_b + i*C, cur,
                                  ln2_w + i*C, ln2_b + i*C,
                                  mlp_w1 + (size_t)i*C*512, mlp_b1 + i*512,
                                  pH, i);
            k_fc2G<<<gBlk, 128>>>(pH, mlp_w2 + (size_t)i*512*C, mlp_b2 + i*C,
                                  cur, alt, pos, i);
            float* tmp = cur; cur = alt; alt = tmp;
        } else {
            k_pf1D<<<gBlk, 128>>>(pO, out_w + (size_t)i*C*C, out_b + i*C, cur,
                                  ln2_w + i*C, ln2_b + i*C,
                                  mlp_w1 + (size_t)i*C*512, mlp_b1 + i*512, pH);
            k_fc2D<<<gBlk, 128>>>(pH, mlp_w2 + (size_t)i*512*C, mlp_b2 + i*C,
                                  cur, out, finalN);
        }
    }
}

// round 16
// speedup vs baseline: 1.0453x; 1.0124x over previous
#include <cuda_runtime.h>
#include <math.h>

#define MAXN 1025
#define BATCH 8
#define C 128
#define NH 8
#define HD 16
#define L 4
#define TKA 128

typedef unsigned long long ull;

// ---------------- packed fp32x2 helpers (sm_103a FFMA2 path) ---------------
__device__ __forceinline__ ull pack2(float lo, float hi) {
    ull r; asm("mov.b64 %0, {%1, %2};" : "=l"(r) : "f"(lo), "f"(hi)); return r;
}
__device__ __forceinline__ float2 unpack2(ull v) {
    float lo, hi; asm("mov.b64 {%0, %1}, %2;" : "=f"(lo), "=f"(hi) : "l"(v));
    return make_float2(lo, hi);
}
__device__ __forceinline__ ull fma2(ull a, ull b, ull c) {
    ull d; asm("fma.rn.f32x2 %0, %1, %2, %3;" : "=l"(d) : "l"(a), "l"(b), "l"(c));
    return d;
}
__device__ __forceinline__ ull mul2(ull a, ull b) {
    ull d; asm("mul.rn.f32x2 %0, %1, %2;" : "=l"(d) : "l"(a), "l"(b));
    return d;
}
__device__ __forceinline__ ull add2(ull a, ull b) {
    ull d; asm("add.rn.f32x2 %0, %1, %2;" : "=l"(d) : "l"(a), "l"(b));
    return d;
}

// ---------------- cp.async helper -------------------------------------------
__device__ __forceinline__ void cp_async16(unsigned saddr, const void* gaddr) {
    asm volatile("cp.async.ca.shared.global [%0], [%1], 16;"
                 :: "r"(saddr), "l"(gaddr));
}
#define CP_COMMIT() asm volatile("cp.async.commit_group;" ::: "memory")
#define CP_WAIT(n)  asm volatile("cp.async.wait_group %0;" :: "n"(n) : "memory")

// ---------------- device scratch (static, allocation-free) ----------------
__device__ float g_X0[BATCH*MAXN*C];
__device__ float g_X1[BATCH*MAXN*C];
__device__ float g_Q [BATCH*NH*MAXN*HD];
__device__ float g_K [BATCH*NH*MAXN*HD];
__device__ float g_V [BATCH*NH*MAXN*HD];
__device__ float g_O [BATCH*MAXN*C];
__device__ float g_H [BATCH*MAXN*512];
__device__ float g_CLSP[BATCH*NH*MAXN];
__device__ float g_WT[768*128];
__device__ int   g_order[BATCH][1024];
__device__ int   g_count[BATCH];
__device__ int   g_mk[3];
__device__ int   g_N;
__device__ int   g_done;

// transpose conv_w (128,768) -> (768,128); also does global init
__global__ void k_transpose(const float* __restrict__ w) {
    int k = blockIdx.x, c = threadIdx.x;
    g_WT[k*128 + c] = w[c*768 + k];
    if (k == 0 && c == 0) {
        g_N = MAXN;
        g_mk[0] = 0; g_mk[1] = 0; g_mk[2] = 0;
        g_done = 0;
    }
}

// ---------------- patch embed + cls row ------------------------------------
__global__ void __launch_bounds__(128) k_patch(
        const float* __restrict__ x, const float* __restrict__ cb,
        const float* __restrict__ cls, const float* __restrict__ pos,
        float* __restrict__ X) {
    int b = blockIdx.y;
    int tid = threadIdx.x;
    if (blockIdx.x == 64) {
        X[(size_t)b*MAXN*C + tid] = cls[tid] + pos[tid];
        return;
    }
    int t0 = blockIdx.x * 16;
    __shared__ __align__(16) float sPT[768][16];
    for (int v = tid; v < 768*16; v += 128) {
        int p = v & 15, k = v >> 4;
        int t = t0 + p;
        int ph = t >> 5, pw = t & 31;
        int ch = k >> 8, rem = k & 255, py = rem >> 4, px = rem & 15;
        sPT[k][p] = x[((size_t)(b*3 + ch)*512 + ph*16 + py)*512 + pw*16 + px];
    }
    __syncthreads();
    float bias = cb[tid];
    ull acc2[8];
    ull bini = pack2(bias, bias);
    #pragma unroll
    for (int j = 0; j < 8; j++) acc2[j] = bini;
    #pragma unroll 4
    for (int k = 0; k < 768; k++) {
        float w = g_WT[k*128 + tid];
        ull w2 = pack2(w, w);
        const ulonglong2* yr = (const ulonglong2*)&sPT[k][0];
        ulonglong2 y0 = yr[0], y1 = yr[1], y2 = yr[2], y3 = yr[3];
        acc2[0] = fma2(w2, y0.x, acc2[0]); acc2[1] = fma2(w2, y0.y, acc2[1]);
        acc2[2] = fma2(w2, y1.x, acc2[2]); acc2[3] = fma2(w2, y1.y, acc2[3]);
        acc2[4] = fma2(w2, y2.x, acc2[4]); acc2[5] = fma2(w2, y2.y, acc2[5]);
        acc2[6] = fma2(w2, y3.x, acc2[6]); acc2[7] = fma2(w2, y3.y, acc2[7]);
    }
    #pragma unroll
    for (int j = 0; j < 8; j++) {
        float2 u = unpack2(acc2[j]);
        int t = t0 + 2*j;
        X[((size_t)b*MAXN + 1 + t)*C + tid]     = u.x + pos[(1 + t)*C + tid];
        X[((size_t)b*MAXN + 2 + t)*C + tid]     = u.y + pos[(2 + t)*C + tid];
    }
}

// ---------------- LN helper (16 tokens, 128 threads) -----------------------
#define LN16_BODY(lwp, lbp)                                                     \
    {                                                                           \
        _Pragma("unroll")                                                       \
        for (int p = 0; p < 16; p++) {                                          \
            float s = xv[p];                                                    \
            _Pragma("unroll")                                                   \
            for (int o = 16; o; o >>= 1) s += __shfl_xor_sync(~0u, s, o);       \
            if (!lane) sRed[0][wid][p] = s;                                     \
        }                                                                       \
        __syncthreads();                                                        \
        _Pragma("unroll")                                                       \
        for (int p = 0; p < 16; p++) {                                          \
            float mu = (sRed[0][0][p] + sRed[0][1][p] + sRed[0][2][p]           \
                        + sRed[0][3][p]) * 0.0078125f;                          \
            float d = xv[p] - mu; xv[p] = d;                                    \
            float s = d * d;                                                    \
            _Pragma("unroll")                                                   \
            for (int o = 16; o; o >>= 1) s += __shfl_xor_sync(~0u, s, o);       \
            if (!lane) sRed[1][wid][p] = s;                                     \
        }                                                                       \
        __syncthreads();                                                        \
        float wgt = (lwp)[tid], bia = (lbp)[tid];                               \
        _Pragma("unroll")                                                       \
        for (int p4 = 0; p4 < 4; p4++) {                                        \
            float4 pk;                                                          \
            float* pkf = (float*)&pk;                                           \
            _Pragma("unroll")                                                   \
            for (int j = 0; j < 4; j++) {                                       \
                int p = 4*p4 + j;                                               \
                float var = (sRed[1][0][p] + sRed[1][1][p] + sRed[1][2][p]      \
                             + sRed[1][3][p]) * 0.0078125f;                     \
                pkf[j] = xv[p] * rsqrtf(var + 1e-5f) * wgt + bia;               \
            }                                                                   \
            sYT[tid][p4] = pk;                                                  \
        }                                                                       \
        __syncthreads();                                                        \
    }

// QKV matmul from sYT + head-major store.
#define QKV_BODY(Wp, bp, writeGuard0, writeGuard1, TOK0, TOK1)                  \
    {                                                                           \
        float b0 = (bp)[tid], b1 = (bp)[tid + 128], b2 = (bp)[tid + 256];       \
        ull a0[8], a1[8], a2[8];                                                \
        ull i0 = pack2(b0, b0), i1 = pack2(b1, b1), i2 = pack2(b2, b2);         \
        _Pragma("unroll")                                                       \
        for (int j = 0; j < 8; j++) { a0[j] = i0; a1[j] = i1; a2[j] = i2; }     \
        _Pragma("unroll 4")                                                     \
        for (int k = 0; k < 128; k++) {                                         \
            float w0 = (Wp)[k*384 + tid];                                       \
            float w1 = (Wp)[k*384 + 128 + tid];                                 \
            float w2 = (Wp)[k*384 + 256 + tid];                                 \
            ull w02 = pack2(w0, w0), w12 = pack2(w1, w1), w22 = pack2(w2, w2);  \
            const ulonglong2* yr = (const ulonglong2*)&sYT[k][0];               \
            ulonglong2 y0 = yr[0], y1 = yr[1], y2 = yr[2], y3 = yr[3];          \
            ull yv8[8] = {y0.x, y0.y, y1.x, y1.y, y2.x, y2.y, y3.x, y3.y};      \
            _Pragma("unroll")                                                   \
            for (int j = 0; j < 8; j++) {                                       \
                a0[j] = fma2(w02, yv8[j], a0[j]);                               \
                a1[j] = fma2(w12, yv8[j], a1[j]);                               \
                a2[j] = fma2(w22, yv8[j], a2[j]);                               \
            }                                                                   \
        }                                                                       \
        int h = tid >> 4, d = tid & 15;                                         \
        size_t hb = (size_t)(b*NH + h)*MAXN;                                    \
        _Pragma("unroll")                                                       \
        for (int j = 0; j < 8; j++) {                                           \
            float2 q2 = unpack2(a0[j]);                                         \
            float2 k2 = unpack2(a1[j]);                                         \
            float2 v2 = unpack2(a2[j]);                                         \
            int p0 = 2*j, p1 = 2*j + 1;                                         \
            if (writeGuard0) {                                                  \
                size_t o = (hb + (TOK0))*HD + d;                                \
                Qo[o] = q2.x; Ko[o] = k2.x; Vo[o] = v2.x;                       \
            }                                                                   \
            if (writeGuard1) {                                                  \
                size_t o = (hb + (TOK1))*HD + d;                                \
                Qo[o] = q2.y; Ko[o] = k2.y; Vo[o] = v2.y;                       \
            }                                                                   \
        }                                                                       \
    }

// slot -> src gather table (16 slots per CTA); slot 0 = CLS
#define GATHER_SETUP(pi)                                                        \
    int mk1 = 1 + g_mk[pi];                                                     \
    if (s0 >= mk1) return;                                                      \
    int tid = threadIdx.x;                                                      \
    __shared__ int sSrc[16];                                                    \
    __shared__ int sVal[16];                                                    \
    if (tid < 16) {                                                             \
        int slot = s0 + tid;                                                    \
        int valid = 0, src = 0;                                                 \
        if (slot == 0) { valid = 1; src = 0; }                                  \
        else if (slot < mk1 && slot - 1 < g_count[b]) {                         \
            valid = 1; src = 1 + g_order[b][slot - 1];                          \
        }                                                                       \
        sSrc[tid] = src; sVal[tid] = valid;                                     \
    }

// ---------------- LN + qkv -> head-major Q,K,V (layer 0) --------------------
__global__ void __launch_bounds__(128) k_qkvln(
        const float* __restrict__ X, const float* __restrict__ lw,
        const float* __restrict__ lb, const float* __restrict__ W,
        const float* __restrict__ bias,
        float* __restrict__ Qo, float* __restrict__ Ko, float* __restrict__ Vo) {
    int b = blockIdx.y;
    int n0 = blockIdx.x * 16;
    int N = g_N;
    if (n0 >= N) return;
    int tid = threadIdx.x, wid = tid >> 5, lane = tid & 31;
    __shared__ float4 sYT[128][4];
    __shared__ float sRed[2][4][16];
    float xv[16];
    #pragma unroll
    for (int p = 0; p < 16; p++) {
        int n = n0 + p;
        xv[p] = (n < N) ? X[((size_t)b*MAXN + n)*C + tid] : 0.0f;
    }
    LN16_BODY(lw, lb)
    QKV_BODY(W, bias, (n0 + p0 < N), (n0 + p1 < N), n0 + p0, n0 + p1)
}

// ---------------- attention v8: split-K + cp.async double buffering ---------
__global__ void __launch_bounds__(128) k_attn8(
        const float* __restrict__ Q, const float* __restrict__ K,
        const float* __restrict__ V, float* __restrict__ O) {
    int N = g_N;
    int bh = blockIdx.y;
    int b = bh >> 3, h = bh & 7;
    int q0 = blockIdx.x * 64;
    if (q0 >= N) return;
    int tid = threadIdx.x, w = tid >> 5, lane = tid & 31;

    __shared__ __align__(16) float sMem[8192];
    unsigned sBase = (unsigned)__cvta_generic_to_shared(sMem);

    const float4* K4 = (const float4*)(K + (size_t)bh*MAXN*HD);
    const float4* V4 = (const float4*)(V + (size_t)bh*MAXN*HD);
    int qA = q0 + lane;
    int qB = q0 + 32 + lane;
    bool vA = qA < N, vB = qB < N;

    ull qa[8], qb[8];
    ull qs = pack2(0.25f, 0.25f);
    #pragma unroll
    for (int j = 0; j < 8; j++) { qa[j] = 0ull; qb[j] = 0ull; }
    if (vA) {
        const float4* Q4 = (const float4*)(Q + ((size_t)bh*MAXN + qA)*HD);
        #pragma unroll
        for (int j = 0; j < 4; j++) {
            float4 t = Q4[j];
            qa[2*j]   = mul2(pack2(t.x, t.y), qs);
            qa[2*j+1] = mul2(pack2(t.z, t.w), qs);
        }
    }
    if (vB) {
        const float4* Q4 = (const float4*)(Q + ((size_t)bh*MAXN + qB)*HD);
        #pragma unroll
        for (int j = 0; j < 4; j++) {
            float4 t = Q4[j];
            qb[2*j]   = mul2(pack2(t.x, t.y), qs);
            qb[2*j+1] = mul2(pack2(t.z, t.w), qs);
        }
    }

    float lA = 0.0f, lB = 0.0f;
    ull accA[8], accB[8];
    #pragma unroll
    for (int j = 0; j < 8; j++) { accA[j] = 0ull; accB[j] = 0ull; }

    int nt = (N + TKA - 1) / TKA;

    {
        int kn0 = min(TKA, N);
        int lim = kn0 * 4;
        for (int i = tid; i < lim; i += 128) {
            unsigned dk = sBase + ((unsigned)i << 4);
            unsigned dv = dk + 8192u;
            cp_async16(dk, K4 + i);
            cp_async16(dv, V4 + i);
        }
        CP_COMMIT();
    }

    for (int t = 0; t < nt; t++) {
        int cur = t & 1;
        if (t + 1 < nt) {
            int nb = (t + 1) * TKA;
            int knn = min(TKA, N - nb);
            int lim = knn * 4;
            unsigned so = sBase + (unsigned)((cur ^ 1) * 16384);
            const float4* gk = K4 + nb*4;
            const float4* gv = V4 + nb*4;
            for (int i = tid; i < lim; i += 128) {
                unsigned dk = so + ((unsigned)i << 4);
                unsigned dv = dk + 8192u;
                cp_async16(dk, gk + i);
                cp_async16(dv, gv + i);
            }
            CP_COMMIT();
            CP_WAIT(1);
        } else {
            CP_WAIT(0);
        }
        __syncthreads();

        int base = t * TKA;
        int kn = min(TKA, N - base);
        const float4* sK = (const float4*)(sMem + cur*4096);
        const float4* sV = (const float4*)(sMem + cur*4096 + 2048);
        int lo = w * 32;
        int hi = min(kn, lo + 32);
        #pragma unroll 2
        for (int m = lo; m < hi; m++) {
            const ulonglong2* kp = (const ulonglong2*)&sK[m*4];
            ulonglong2 k0 = kp[0], k1 = kp[1], k2 = kp[2], k3 = kp[3];
            ull sa = fma2(qa[1], k0.y, mul2(qa[0], k0.x));
            ull sb = fma2(qa[3], k1.y, mul2(qa[2], k1.x));
            ull sc = fma2(qa[5], k2.y, mul2(qa[4], k2.x));
            ull sd = fma2(qa[7], k3.y, mul2(qa[6], k3.x));
            ull stA = add2(add2(sa, sb), add2(sc, sd));
            ull ta = fma2(qb[1], k0.y, mul2(qb[0], k0.x));
            ull tb = fma2(qb[3], k1.y, mul2(qb[2], k1.x));
            ull tc = fma2(qb[5], k2.y, mul2(qb[4], k2.x));
            ull td = fma2(qb[7], k3.y, mul2(qb[6], k3.x));
            ull stB = add2(add2(ta, tb), add2(tc, td));
            float2 spA = unpack2(stA);
            float2 spB = unpack2(stB);
            float eA = __expf(spA.x + spA.y);
            float eB = __expf(spB.x + spB.y);
            lA += eA; lB += eB;
            ull eA2 = pack2(eA, eA);
            ull eB2 = pack2(eB, eB);
            const ulonglong2* vp = (const ulonglong2*)&sV[m*4];
            ulonglong2 v0 = vp[0], v1 = vp[1], v2 = vp[2], v3 = vp[3];
            accA[0] = fma2(eA2, v0.x, accA[0]); accB[0] = fma2(eB2, v0.x, accB[0]);
            accA[1] = fma2(eA2, v0.y, accA[1]); accB[1] = fma2(eB2, v0.y, accB[1]);
            accA[2] = fma2(eA2, v1.x, accA[2]); accB[2] = fma2(eB2, v1.x, accB[2]);
            accA[3] = fma2(eA2, v1.y, accA[3]); accB[3] = fma2(eB2, v1.y, accB[3]);
            accA[4] = fma2(eA2, v2.x, accA[4]); accB[4] = fma2(eB2, v2.x, accB[4]);
            accA[5] = fma2(eA2, v2.y, accA[5]); accB[5] = fma2(eB2, v2.y, accB[5]);
            accA[6] = fma2(eA2, v3.x, accA[6]); accB[6] = fma2(eB2, v3.x, accB[6]);
            accA[7] = fma2(eA2, v3.y, accA[7]); accB[7] = fma2(eB2, v3.y, accB[7]);
        }
        __syncthreads();
    }

    float (*sAcc)[64][17] = (float (*)[64][17])sMem;

    #pragma unroll
    for (int j = 0; j < 8; j++) {
        float2 uA = unpack2(accA[j]);
        float2 uB = unpack2(accB[j]);
        sAcc[w][lane][2*j]      = uA.x;
        sAcc[w][lane][2*j+1]    = uA.y;
        sAcc[w][32+lane][2*j]   = uB.x;
        sAcc[w][32+lane][2*j+1] = uB.y;
    }
    sAcc[w][lane][16]    = lA;
    sAcc[w][32+lane][16] = lB;
    __syncthreads();

    int j = tid >> 1, half = tid & 1;
    int q = q0 + j;
    if (q < N) {
        float lsum = (sAcc[0][j][16] + sAcc[1][j][16])
                   + (sAcc[2][j][16] + sAcc[3][j][16]);
        float inv = 1.0f / lsum;
        int d0 = half * 8;
        float o[8];
        #pragma unroll
        for (int d = 0; d < 8; d++) {
            o[d] = ((sAcc[0][j][d0+d] + sAcc[1][j][d0+d])
                  + (sAcc[2][j][d0+d] + sAcc[3][j][d0+d])) * inv;
        }
        float* op = O + ((size_t)b*MAXN + q)*C + h*HD + d0;
        ((float4*)op)[0] = make_float4(o[0], o[1], o[2], o[3]);
        ((float4*)op)[1] = make_float4(o[4], o[5], o[6], o[7]);
        if (!half) {
            const float4* Q4 = (const float4*)(Q + ((size_t)bh*MAXN + q)*HD);
            float qv[16];
            #pragma unroll
            for (int i = 0; i < 4; i++) {
                float4 tq = Q4[i];
                qv[4*i]   = tq.x * 0.25f; qv[4*i+1] = tq.y * 0.25f;
                qv[4*i+2] = tq.z * 0.25f; qv[4*i+3] = tq.w * 0.25f;
            }
            const float* k0 = K + (size_t)bh*MAXN*HD;
            float sa_l = fmaf(qv[2],  k0[2],  qv[0]*k0[0]);
            float sa_h = fmaf(qv[3],  k0[3],  qv[1]*k0[1]);
            float sb_l = fmaf(qv[6],  k0[6],  qv[4]*k0[4]);
            float sb_h = fmaf(qv[7],  k0[7],  qv[5]*k0[5]);
            float sc_l = fmaf(qv[10], k0[10], qv[8]*k0[8]);
            float sc_h = fmaf(qv[11], k0[11], qv[9]*k0[9]);
            float sd_l = fmaf(qv[14], k0[14], qv[12]*k0[12]);
            float sd_h = fmaf(qv[15], k0[15], qv[13]*k0[13]);
            float slo = (sa_l + sb_l) + (sc_l + sd_l);
            float shi = (sa_h + sb_h) + (sc_h + sd_h);
            g_CLSP[(size_t)bh*MAXN + q] = __expf(slo + shi) * inv;
        }
    }
}

// ---------------- prune (warp-shuffle scan/argmax + folded g_N) -------------
__global__ void k_prune1(float thresh, int pi) {
    int b = blockIdx.x;
    int t = threadIdx.x;
    int lane = t & 31, wid = t >> 5;
    int tc = g_N - 1;
    float am = -1e30f;
    int keep = 0;
    if (t < tc) {
        float s = 0.0f;
        #pragma unroll
        for (int h = 0; h < NH; h++) s += g_CLSP[(b*NH + h)*MAXN + 1 + t];
        am = s * 0.125f;
        keep = (am > thresh) ? 1 : 0;
    }
    int sc = keep;
    #pragma unroll
    for (int o = 1; o < 32; o <<= 1) {
        int v = __shfl_up_sync(~0u, sc, o);
        if (lane >= o) sc += v;
    }
    float bv = am; int bi = t;
    #pragma unroll
    for (int o = 16; o; o >>= 1) {
        float ov = __shfl_xor_sync(~0u, bv, o);
        int   oi = __shfl_xor_sync(~0u, bi, o);
        if (ov > bv || (ov == bv && oi < bi)) { bv = ov; bi = oi; }
    }
    __shared__ int wsum[32], wbi[32], woff[32];
    __shared__ float wbv[32];
    __shared__ int gArg, gTot;
    if (lane == 31) wsum[wid] = sc;
    if (lane == 0) { wbv[wid] = bv; wbi[wid] = bi; }
    __syncthreads();
    if (wid == 0) {
        int v = wsum[lane];
        int s2 = v;
        #pragma unroll
        for (int o = 1; o < 32; o <<= 1) {
            int u = __shfl_up_sync(~0u, s2, o);
            if (lane >= o) s2 += u;
        }
        woff[lane] = s2 - v;
        if (lane == 31) gTot = s2;
        float bv2 = wbv[lane]; int bi2 = wbi[lane];
        #pragma unroll
        for (int o = 16; o; o >>= 1) {
            float ov = __shfl_xor_sync(~0u, bv2, o);
            int   oi = __shfl_xor_sync(~0u, bi2, o);
            if (ov > bv2 || (ov == bv2 && oi < bi2)) { bv2 = ov; bi2 = oi; }
        }
        if (lane == 0) gArg = bi2;
    }
    __syncthreads();
    int total = gTot;
    int posi = woff[wid] + sc;
    if (total > 0 && keep) g_order[b][posi - 1] = t;
    if (t == 0) {
        int cnt = total;
        if (total == 0) { g_order[b][0] = gArg; cnt = 1; }
        g_count[b] = cnt;
        atomicMax(&g_mk[pi], cnt);
        __threadfence();
        int tk = atomicAdd(&g_done, 1);
        if (tk == BATCH - 1) {
            g_N = 1 + g_mk[pi];
            g_done = 0;
        }
    }
}

// ---------- fused gathered proj + LN2 + fc1 + gelu (layers 0-2) -------------
__global__ void __launch_bounds__(128) k_pf1G(
        const float* __restrict__ Oin, const float* __restrict__ Wp,
        const float* __restrict__ bp, float* __restrict__ X,
        const float* __restrict__ lw, const float* __restrict__ lb,
        const float* __restrict__ W1, const float* __restrict__ b1,
        float* __restrict__ H, int pi) {
    int b = blockIdx.y;
    int s0 = blockIdx.x * 16;
    GATHER_SETUP(pi)
    int wid = tid >> 5, lane = tid & 31;
    __shared__ __align__(16) float sOT[128][16];
    __shared__ float4 sYT[128][4];
    __shared__ float sRed[2][4][16];
    __syncthreads();
    const float4* O4 = (const float4*)Oin;
    for (int v = tid; v < 16*32; v += 128) {
        int p = v & 15, kq = v >> 4;
        float4 o4 = sVal[p] ? O4[((size_t)b*MAXN + sSrc[p])*32 + kq]
                            : make_float4(0.f, 0.f, 0.f, 0.f);
        sOT[4*kq+0][p] = o4.x; sOT[4*kq+1][p] = o4.y;
        sOT[4*kq+2][p] = o4.z; sOT[4*kq+3][p] = o4.w;
    }
    __syncthreads();
    float bs = bp[tid];
    ull acc2[8];
    ull bini = pack2(bs, bs);
    #pragma unroll
    for (int j = 0; j < 8; j++) acc2[j] = bini;
    #pragma unroll 4
    for (int k = 0; k < 128; k++) {
        float w = Wp[k*128 + tid];
        ull w2 = pack2(w, w);
        const ulonglong2* yr = (const ulonglong2*)&sOT[k][0];
        ulonglong2 y0 = yr[0], y1 = yr[1], y2 = yr[2], y3 = yr[3];
        acc2[0] = fma2(w2, y0.x, acc2[0]); acc2[1] = fma2(w2, y0.y, acc2[1]);
        acc2[2] = fma2(w2, y1.x, acc2[2]); acc2[3] = fma2(w2, y1.y, acc2[3]);
        acc2[4] = fma2(w2, y2.x, acc2[4]); acc2[5] = fma2(w2, y2.y, acc2[5]);
        acc2[6] = fma2(w2, y3.x, acc2[6]); acc2[7] = fma2(w2, y3.y, acc2[7]);
    }
    float xv[16];
    #pragma unroll
    for (int j = 0; j < 8; j++) {
        float2 u = unpack2(acc2[j]);
        int p0 = 2*j, p1 = 2*j + 1;
        if (sVal[p0]) {
            float t0 = X[((size_t)b*MAXN + sSrc[p0])*C + tid] + u.x;
            X[((size_t)b*MAXN + sSrc[p0])*C + tid] = t0;
            xv[p0] = t0;
        } else xv[p0] = 0.0f;
        if (sVal[p1]) {
            float t1 = X[((size_t)b*MAXN + sSrc[p1])*C + tid] + u.y;
            X[((size_t)b*MAXN + sSrc[p1])*C + tid] = t1;
            xv[p1] = t1;
        } else xv[p1] = 0.0f;
    }
    LN16_BODY(lw, lb)
    const float4* W4 = (const float4*)W1;
    float4 b4 = ((const float4*)b1)[tid];
    ull a0[8], a1[8], a2[8], a3[8];
    ull i0 = pack2(b4.x, b4.x), i1 = pack2(b4.y, b4.y);
    ull i2 = pack2(b4.z, b4.z), i3 = pack2(b4.w, b4.w);
    #pragma unroll
    for (int j = 0; j < 8; j++) { a0[j]=i0; a1[j]=i1; a2[j]=i2; a3[j]=i3; }
    #pragma unroll 2
    for (int k = 0; k < 128; k++) {
        float4 w4 = W4[k*128 + tid];
        ull w0 = pack2(w4.x, w4.x), w1 = pack2(w4.y, w4.y);
        ull w2 = pack2(w4.z, w4.z), w3 = pack2(w4.w, w4.w);
        const ulonglong2* yr = (const ulonglong2*)&sYT[k][0];
        ulonglong2 y0 = yr[0], y1 = yr[1], y2 = yr[2], y3 = yr[3];
        ull yv8[8] = {y0.x, y0.y, y1.x, y1.y, y2.x, y2.y, y3.x, y3.y};
        #pragma unroll
        for (int j = 0; j < 8; j++) {
            a0[j] = fma2(w0, yv8[j], a0[j]);
            a1[j] = fma2(w1, yv8[j], a1[j]);
            a2[j] = fma2(w2, yv8[j], a2[j]);
            a3[j] = fma2(w3, yv8[j], a3[j]);
        }
    }
    float4* H4 = (float4*)H;
    #pragma unroll
    for (int j = 0; j < 8; j++) {
        float2 u0 = unpack2(a0[j]);
        float2 u1 = unpack2(a1[j]);
        float2 u2 = unpack2(a2[j]);
        float2 u3 = unpack2(a3[j]);
        int slot = s0 + 2*j;
        if (slot < mk1) {
            float4 hv;
            hv.x = 0.5f*u0.x*(1.0f + erff(u0.x*0.70710678118654752f));
            hv.y = 0.5f*u1.x*(1.0f + erff(u1.x*0.70710678118654752f));
            hv.z = 0.5f*u2.x*(1.0f + erff(u2.x*0.70710678118654752f));
            hv.w = 0.5f*u3.x*(1.0f + erff(u3.x*0.70710678118654752f));
            H4[((size_t)b*MAXN + slot)*128 + tid] = hv;
        }
        if (slot + 1 < mk1) {
            float4 hv;
            hv.x = 0.5f*u0.y*(1.0f + erff(u0.y*0.70710678118654752f));
            hv.y = 0.5f*u1.y*(1.0f + erff(u1.y*0.70710678118654752f));
            hv.z = 0.5f*u2.y*(1.0f + erff(u2.y*0.70710678118654752f));
            hv.w = 0.5f*u3.y*(1.0f + erff(u3.y*0.70710678118654752f));
            H4[((size_t)b*MAXN + slot + 1)*128 + tid] = hv;
        }
    }
}

// ---------- fused dense proj + LN2 + fc1 + gelu (layer 3) -------------------
__global__ void __launch_bounds__(128) k_pf1D(
        const float* __restrict__ Oin, const float* __restrict__ Wp,
        const float* __restrict__ bp, float* __restrict__ X,
        const float* __restrict__ lw, const float* __restrict__ lb,
        const float* __restrict__ W1, const float* __restrict__ b1,
        float* __restrict__ H) {
    int b = blockIdx.y;
    int n0 = blockIdx.x * 16;
    int N = g_N;
    if (n0 >= N) return;
    int tid = threadIdx.x, wid = tid >> 5, lane = tid & 31;
    __shared__ __align__(16) float sOT[128][16];
    __shared__ float4 sYT[128][4];
    __shared__ float sRed[2][4][16];
    const float4* O4 = (const float4*)Oin;
    for (int v = tid; v < 16*32; v += 128) {
        int p = v & 15, kq = v >> 4;
        int n = n0 + p;
        float4 o4 = (n < N) ? O4[((size_t)b*MAXN + n)*32 + kq]
                            : make_float4(0.f, 0.f, 0.f, 0.f);
        sOT[4*kq+0][p] = o4.x; sOT[4*kq+1][p] = o4.y;
        sOT[4*kq+2][p] = o4.z; sOT[4*kq+3][p] = o4.w;
    }
    __syncthreads();
    float bs = bp[tid];
    ull acc2[8];
    ull bini = pack2(bs, bs);
    #pragma unroll
    for (int j = 0; j < 8; j++) acc2[j] = bini;
    #pragma unroll 4
    for (int k = 0; k < 128; k++) {
        float w = Wp[k*128 + tid];
        ull w2 = pack2(w, w);
        const ulonglong2* yr = (const ulonglong2*)&sOT[k][0];
        ulonglong2 y0 = yr[0], y1 = yr[1], y2 = yr[2], y3 = yr[3];
        acc2[0] = fma2(w2, y0.x, acc2[0]); acc2[1] = fma2(w2, y0.y, acc2[1]);
        acc2[2] = fma2(w2, y1.x, acc2[2]); acc2[3] = fma2(w2, y1.y, acc2[3]);
        acc2[4] = fma2(w2, y2.x, acc2[4]); acc2[5] = fma2(w2, y2.y, acc2[5]);
        acc2[6] = fma2(w2, y3.x, acc2[6]); acc2[7] = fma2(w2, y3.y, acc2[7]);
    }
    float xv[16];
    #pragma unroll
    for (int j = 0; j < 8; j++) {
        float2 u = unpack2(acc2[j]);
        int n = n0 + 2*j;
        if (n < N) {
            float t0 = X[((size_t)b*MAXN + n)*C + tid] + u.x;
            X[((size_t)b*MAXN + n)*C + tid] = t0;
            xv[2*j] = t0;
        } else xv[2*j] = 0.0f;
        if (n + 1 < N) {
            float t1 = X[((size_t)b*MAXN + n + 1)*C + tid] + u.y;
            X[((size_t)b*MAXN + n + 1)*C + tid] = t1;
            xv[2*j+1] = t1;
        } else xv[2*j+1] = 0.0f;
    }
    LN16_BODY(lw, lb)
    const float4* W4 = (const float4*)W1;
    float4 b4 = ((const float4*)b1)[tid];
    ull a0[8], a1[8], a2[8], a3[8];
    ull i0 = pack2(b4.x, b4.x), i1 = pack2(b4.y, b4.y);
    ull i2 = pack2(b4.z, b4.z), i3 = pack2(b4.w, b4.w);
    #pragma unroll
    for (int j = 0; j < 8; j++) { a0[j]=i0; a1[j]=i1; a2[j]=i2; a3[j]=i3; }
    #pragma unroll 2
    for (int k = 0; k < 128; k++) {
        float4 w4 = W4[k*128 + tid];
        ull w0 = pack2(w4.x, w4.x), w1 = pack2(w4.y, w4.y);
        ull w2 = pack2(w4.z, w4.z), w3 = pack2(w4.w, w4.w);
        const ulonglong2* yr = (const ulonglong2*)&sYT[k][0];
        ulonglong2 y0 = yr[0], y1 = yr[1], y2 = yr[2], y3 = yr[3];
        ull yv8[8] = {y0.x, y0.y, y1.x, y1.y, y2.x, y2.y, y3.x, y3.y};
        #pragma unroll
        for (int j = 0; j < 8; j++) {
            a0[j] = fma2(w0, yv8[j], a0[j]);
            a1[j] = fma2(w1, yv8[j], a1[j]);
            a2[j] = fma2(w2, yv8[j], a2[j]);
            a3[j] = fma2(w3, yv8[j], a3[j]);
        }
    }
    float4* H4 = (float4*)H;
    #pragma unroll
    for (int j = 0; j < 8; j++) {
        float2 u0 = unpack2(a0[j]);
        float2 u1 = unpack2(a1[j]);
        float2 u2 = unpack2(a2[j]);
        float2 u3 = unpack2(a3[j]);
        int n = n0 + 2*j;
        if (n < N) {
            float4 hv;
            hv.x = 0.5f*u0.x*(1.0f + erff(u0.x*0.70710678118654752f));
            hv.y = 0.5f*u1.x*(1.0f + erff(u1.x*0.70710678118654752f));
            hv.z = 0.5f*u2.x*(1.0f + erff(u2.x*0.70710678118654752f));
            hv.w = 0.5f*u3.x*(1.0f + erff(u3.x*0.70710678118654752f));
            H4[((size_t)b*MAXN + n)*128 + tid] = hv;
        }
        if (n + 1 < N) {
            float4 hv;
            hv.x = 0.5f*u0.y*(1.0f + erff(u0.y*0.70710678118654752f));
            hv.y = 0.5f*u1.y*(1.0f + erff(u1.y*0.70710678118654752f));
            hv.z = 0.5f*u2.y*(1.0f + erff(u2.y*0.70710678118654752f));
            hv.w = 0.5f*u3.y*(1.0f + erff(u3.y*0.70710678118654752f));
            H4[((size_t)b*MAXN + n + 1)*128 + tid] = hv;
        }
    }
}

// ---- fused gathered fc2 + compact + pos + LN1(next) + QKV(next) ------------
__global__ void __launch_bounds__(128) k_fc2Gqkv(
        const float* __restrict__ H, const float* __restrict__ W,
        const float* __restrict__ bias, const float* __restrict__ Xold,
        float* __restrict__ Xnew, const float* __restrict__ pos, int pi,
        const float* __restrict__ lwn, const float* __restrict__ lbn,
        const float* __restrict__ Wq, const float* __restrict__ bq,
        float* __restrict__ Qo, float* __restrict__ Ko, float* __restrict__ Vo) {
    int b = blockIdx.y;
    int s0 = blockIdx.x * 16;
    GATHER_SETUP(pi)
    int wid = tid >> 5, lane = tid & 31;
    __shared__ __align__(16) float sHT[512][16];
    __shared__ float4 sYT[128][4];
    __shared__ float sRed[2][4][16];
    __syncthreads();
    const float4* H4 = (const float4*)H;
    for (int v = tid; v < 16*128; v += 128) {
        int p = v & 15, kq = v >> 4;
        int slot = s0 + p;
        float4 h4 = (slot < mk1) ? H4[((size_t)b*MAXN + slot)*128 + kq]
                                 : make_float4(0.f, 0.f, 0.f, 0.f);
        sHT[4*kq+0][p] = h4.x; sHT[4*kq+1][p] = h4.y;
        sHT[4*kq+2][p] = h4.z; sHT[4*kq+3][p] = h4.w;
    }
    __syncthreads();
    float bs = bias[tid];
    ull acc2[8];
    ull bini = pack2(bs, bs);
    #pragma unroll
    for (int j = 0; j < 8; j++) acc2[j] = bini;
    #pragma unroll 4
    for (int k = 0; k < 512; k++) {
        float w = W[k*128 + tid];
        ull w2 = pack2(w, w);
        const ulonglong2* yr = (const ulonglong2*)&sHT[k][0];
        ulonglong2 y0 = yr[0], y1 = yr[1], y2 = yr[2], y3 = yr[3];
        acc2[0] = fma2(w2, y0.x, acc2[0]); acc2[1] = fma2(w2, y0.y, acc2[1]);
        acc2[2] = fma2(w2, y1.x, acc2[2]); acc2[3] = fma2(w2, y1.y, acc2[3]);
        acc2[4] = fma2(w2, y2.x, acc2[4]); acc2[5] = fma2(w2, y2.y, acc2[5]);
        acc2[6] = fma2(w2, y3.x, acc2[6]); acc2[7] = fma2(w2, y3.y, acc2[7]);
    }
    float xv[16];
    #pragma unroll
    for (int j = 0; j < 8; j++) {
        float2 u = unpack2(acc2[j]);
        int p0 = 2*j, p1 = 2*j + 1;
        int slot0 = s0 + p0, slot1 = s0 + p1;
        if (slot0 < mk1) {
            float base = sVal[p0]
                ? Xold[((size_t)b*MAXN + sSrc[p0])*C + tid] + u.x : 0.0f;
            float val = base + pos[slot0*C + tid];
            Xnew[((size_t)b*MAXN + slot0)*C + tid] = val;
            xv[p0] = val;
        } else xv[p0] = 0.0f;
        if (slot1 < mk1) {
            float base = sVal[p1]
                ? Xold[((size_t)b*MAXN + sSrc[p1])*C + tid] + u.y : 0.0f;
            float val = base + pos[slot1*C + tid];
            Xnew[((size_t)b*MAXN + slot1)*C + tid] = val;
            xv[p1] = val;
        } else xv[p1] = 0.0f;
    }
    // LN1(next layer) + QKV(next layer) on the freshly compacted rows
    LN16_BODY(lwn, lbn)
    QKV_BODY(Wq, bq, (s0 + p0 < mk1), (s0 + p1 < mk1), s0 + p0, s0 + p1)
}

// ---------------- dense fc2 (layer 3): writes residual sum to out -----------
__global__ void __launch_bounds__(128) k_fc2D(
        const float* __restrict__ H, const float* __restrict__ W,
        const float* __restrict__ bias, const float* __restrict__ X,
        float* __restrict__ out, int finalN) {
    int b = blockIdx.y;
    int n0 = blockIdx.x * 16;
    int N = g_N;
    if (n0 >= N) return;
    int tid = threadIdx.x;
    __shared__ __align__(16) float sHT[512][16];
    const float4* H4 = (const float4*)H;
    for (int v = tid; v < 16*128; v += 128) {
        int p = v & 15, kq = v >> 4;
        int n = n0 + p;
        float4 h4 = (n < N) ? H4[((size_t)b*MAXN + n)*128 + kq]
                            : make_float4(0.f, 0.f, 0.f, 0.f);
        sHT[4*kq+0][p] = h4.x; sHT[4*kq+1][p] = h4.y;
        sHT[4*kq+2][p] = h4.z; sHT[4*kq+3][p] = h4.w;
    }
    __syncthreads();
    float bs = bias[tid];
    ull acc2[8];
    ull bini = pack2(bs, bs);
    #pragma unroll
    for (int j = 0; j < 8; j++) acc2[j] = bini;
    #pragma unroll 4
    for (int k = 0; k < 512; k++) {
        float w = W[k*128 + tid];
        ull w2 = pack2(w, w);
        const ulonglong2* yr = (const ulonglong2*)&sHT[k][0];
        ulonglong2 y0 = yr[0], y1 = yr[1], y2 = yr[2], y3 = yr[3];
        acc2[0] = fma2(w2, y0.x, acc2[0]); acc2[1] = fma2(w2, y0.y, acc2[1]);
        acc2[2] = fma2(w2, y1.x, acc2[2]); acc2[3] = fma2(w2, y1.y, acc2[3]);
        acc2[4] = fma2(w2, y2.x, acc2[4]); acc2[5] = fma2(w2, y2.y, acc2[5]);
        acc2[6] = fma2(w2, y3.x, acc2[6]); acc2[7] = fma2(w2, y3.y, acc2[7]);
    }
    #pragma unroll
    for (int j = 0; j < 8; j++) {
        float2 u = unpack2(acc2[j]);
        int n = n0 + 2*j;
        if (n < N)
            out[((size_t)b*finalN + n)*C + tid] =
                X[((size_t)b*MAXN + n)*C + tid] + u.x;
        if (n + 1 < N)
            out[((size_t)b*finalN + n + 1)*C + tid] =
                X[((size_t)b*MAXN + n + 1)*C + tid] + u.y;
    }
}

// ---------------- host orchestration ----------------------------------------
extern "C" void kernel_launch(void* const* d_in, const int* in_sizes, int n_in,
                              void* d_out, int out_size) {
    const float* conv_w   = (const float*)d_in[0];
    const float* conv_b   = (const float*)d_in[1];
    const float* cls_tok  = (const float*)d_in[2];
    const float* pos      = (const float*)d_in[3];
    const float* ln1_w    = (const float*)d_in[4];
    const float* ln1_b    = (const float*)d_in[5];
    const float* qkv_w    = (const float*)d_in[6];
    const float* qkv_b    = (const float*)d_in[7];
    const float* out_w    = (const float*)d_in[8];
    const float* out_b    = (const float*)d_in[9];
    const float* ln2_w    = (const float*)d_in[10];
    const float* ln2_b    = (const float*)d_in[11];
    const float* mlp_w1   = (const float*)d_in[12];
    const float* mlp_b1   = (const float*)d_in[13];
    const float* mlp_w2   = (const float*)d_in[14];
    const float* mlp_b2   = (const float*)d_in[15];
    const float* x        = (const float*)d_in[16];
    float* out = (float*)d_out;

    float *pX0, *pX1, *pQ, *pK, *pV, *pO, *pH;
    cudaGetSymbolAddress((void**)&pX0, g_X0);
    cudaGetSymbolAddress((void**)&pX1, g_X1);
    cudaGetSymbolAddress((void**)&pQ,  g_Q);
    cudaGetSymbolAddress((void**)&pK,  g_K);
    cudaGetSymbolAddress((void**)&pV,  g_V);
    cudaGetSymbolAddress((void**)&pO,  g_O);
    cudaGetSymbolAddress((void**)&pH,  g_H);

    const float THRESH[3] = {0.001f, 0.0012f, 0.0015f};
    int finalN = out_size / (BATCH * C);

    k_transpose<<<768, 128>>>(conv_w);
    k_patch<<<dim3(65, BATCH), 128>>>(x, conv_b, cls_tok, pos, pX0);

    float* cur = pX0;
    float* alt = pX1;
    dim3 gBlk(65, BATCH);
    dim3 gAtt((MAXN + 63)/64, BATCH*NH);

    k_qkvln<<<gBlk, 128>>>(cur, ln1_w, ln1_b, qkv_w, qkv_b, pQ, pK, pV);

    for (int i = 0; i < L; i++) {
        k_attn8<<<gAtt, 128>>>(pQ, pK, pV, pO);
        if (i < L - 1) {
            k_prune1<<<BATCH, 1024>>>(THRESH[i], i);
            k_pf1G<<<gBlk, 128>>>(pO, out_w + (size_t)i*C*C, out_b + i*C, cur,
                                  ln2_w + i*C, ln2_b + i*C,
                                  mlp_w1 + (size_t)i*C*512, mlp_b1 + i*512,
                                  pH, i);
            k_fc2Gqkv<<<gBlk, 128>>>(pH, mlp_w2 + (size_t)i*512*C, mlp_b2 + i*C,
                                     cur, alt, pos, i,
                                     ln1_w + (i+1)*C, ln1_b + (i+1)*C,
                                     qkv_w + (size_t)(i+1)*C*384,
                                     qkv_b + (i+1)*384,
                                     pQ, pK, pV);
            float* tmp = cur; cur = alt; alt = tmp;
        } else {
            k_pf1D<<<gBlk, 128>>>(pO, out_w + (size_t)i*C*C, out_b + i*C, cur,
                                  ln2_w + i*C, ln2_b + i*C,
                                  mlp_w1 + (size_t)i*C*512, mlp_b1 + i*512, pH);
            k_fc2D<<<gBlk, 128>>>(pH, mlp_w2 + (size_t)i*512*C, mlp_b2 + i*C,
                                  cur, out, finalN);
        }
    }
}